// round 9
// baseline (speedup 1.0000x reference)
#include <cuda_runtime.h>
#include <cuda_bf16.h>
#include <math.h>
#include <cstdint>

#define NPTS   16384
#define NB     16
#define NSLOT  32          // 16 source + 16 target clouds
#define KKP    16
#define OUT_DEF (NB*NPTS*3)   // 786432
#define OUT_KP  (NB*KKP*3)    // 768
#define BN_EPS 1e-5f

// ----------------------------------------------------------------------------
// bf16 2-way split: v = h + m + r, |r| <= ~2^-18 |v|
// ----------------------------------------------------------------------------
__device__ __forceinline__ void bsplit2(float v, unsigned short &h, unsigned short &m) {
    __nv_bfloat16 bh = __float2bfloat16(v);
    float r = v - __bfloat162float(bh);
    __nv_bfloat16 bm = __float2bfloat16(r);
    h = __bfloat16_as_ushort(bh);
    m = __bfloat16_as_ushort(bm);
}
// pack two adjacent values -> (hi-word pair, lo-word pair)
__device__ __forceinline__ void pack_split(float v0, float v1, uint32_t &ph, uint32_t &pm) {
    unsigned short h0, m0, h1, m1;
    bsplit2(v0, h0, m0); bsplit2(v1, h1, m1);
    ph = (uint32_t)h0 | ((uint32_t)h1 << 16);
    pm = (uint32_t)m0 | ((uint32_t)m1 << 16);
}

// bf16 m16n8k16 MMA, fp32 accumulate (baseline PTX, works on compute_103)
#define MMA_BF16(acc, A, B) \
    asm volatile("mma.sync.aligned.m16n8k16.row.col.f32.bf16.bf16.f32 " \
        "{%0,%1,%2,%3}, {%4,%5,%6,%7}, {%8,%9}, {%0,%1,%2,%3};" \
        : "+f"((acc)[0]), "+f"((acc)[1]), "+f"((acc)[2]), "+f"((acc)[3]) \
        : "r"((A)[0]), "r"((A)[1]), "r"((A)[2]), "r"((A)[3]), \
          "r"((B)[0]), "r"((B)[1]))

// ----------------------------------------------------------------------------
// Device scratch (no allocations allowed)
// Interleaved (hi,lo) uint2 layout; strides in uint2 units, all ≡ 4 (mod 16)
// so LDS.64 lane addr mod 16 = 4g+tq -> conflict-free per half-warp phase.
// ----------------------------------------------------------------------------
#define WS2 36   // W2 kpair stride (32 pairs + 4 pad)
#define WS3 68   // W3 kpair stride (64 pairs + 4 pad)
#define HS1 36   // H1 kpair stride
#define HS2 68   // H2 kpair stride

__device__ float g_w1f[64*3];
__device__ float g_b1f[64];
__device__ uint2 g_w2p[128*WS2];   // (hi,lo) packed bf16x2 pairs, [n][kpair]
__device__ float g_b2f[128];
__device__ uint2 g_w3p[128*WS3];
__device__ float g_b3f[128];
__device__ int   g_lat[NSLOT*128]; // latent max (float bits; relu => >=0)
__device__ float g_kp[NSLOT*48];
__device__ float g_sel[NSLOT*48];
__device__ float g_cage[NB*1536];
__device__ float g_pmm[NB*6];

// ----------------------------------------------------------------------------
// Prep: fold BN into weights, 2-way bf16 split, pack interleaved k-pairs
// ----------------------------------------------------------------------------
__global__ void prep_kernel(
    const float* w1, const float* b1, const float* g1, const float* be1,
    const float* m1, const float* v1,
    const float* w2, const float* b2, const float* g2, const float* be2,
    const float* m2, const float* v2,
    const float* w3, const float* b3, const float* g3, const float* be3,
    const float* m3, const float* v3)
{
    int t = threadIdx.x;
    for (int d = t; d < 64; d += 256) {
        float s = g1[d] * rsqrtf(v1[d] + BN_EPS);
        g_w1f[d*3+0] = w1[d*3+0]*s;
        g_w1f[d*3+1] = w1[d*3+1]*s;
        g_w1f[d*3+2] = w1[d*3+2]*s;
        g_b1f[d] = (b1[d]-m1[d])*s + be1[d];
    }
    for (int d = t; d < 128; d += 256) {
        float s2 = g2[d] * rsqrtf(v2[d] + BN_EPS);
        for (int k = 0; k < 64; k += 2) {
            uint32_t ph, pm;
            pack_split(w2[d*64+k]*s2, w2[d*64+k+1]*s2, ph, pm);
            g_w2p[d*WS2 + (k>>1)] = make_uint2(ph, pm);
        }
        g_b2f[d] = (b2[d]-m2[d])*s2 + be2[d];
        float s3 = g3[d] * rsqrtf(v3[d] + BN_EPS);
        for (int k = 0; k < 128; k += 2) {
            uint32_t ph, pm;
            pack_split(w3[d*128+k]*s3, w3[d*128+k+1]*s3, ph, pm);
            g_w3p[d*WS3 + (k>>1)] = make_uint2(ph, pm);
        }
        g_b3f[d] = (b3[d]-m3[d])*s3 + be3[d];
    }
    for (int i = t; i < NSLOT*128; i += 256) g_lat[i] = 0;
}

// ----------------------------------------------------------------------------
// Encoder: 3->64->128->128 MLP + segmented max, layers 2/3 on bf16 m16n8k16
// mma.sync, 2-way split, 3 terms (hh+hm+mh). Interleaved (hi,lo) uint2 smem:
// every fragment operand is ONE LDS.64 delivering both split words.
// Per k16-step per warp: 8 A-LDS.64 + 8 B-LDS.64 + 24 HMMA (was 32 LDS.32).
// Block 256 threads (8 warps), subtile 64 pts; warp owns 32 pts x 32 dims.
// Fragments (m16n8k16, g=lane>>2, tq=lane&3):
//   A: [row g][kp tq], [g+8][tq], [g][tq+4], [g+8][tq+4]
//   B: [n=g][kp tq], [n=g][kp tq+4]
//   D: c0=(g,2tq) c1=(g,2tq+1) c2=(g+8,2tq) c3=(g+8,2tq+1)
// ----------------------------------------------------------------------------
#define ENC_TP   64
#define ENC_SUBT 8
#define ENC_SMEM_BYTES ((128*WS2 + 128*WS3 + 64*HS1 + 64*HS2)*8 + (192+256)*4)

extern __shared__ uint2 enc_smem[];

__global__ __launch_bounds__(256, 1)
void enc_kernel(const float* __restrict__ src, const float* __restrict__ tgt)
{
    uint2* sW2 = enc_smem;            // 128*WS2
    uint2* sW3 = sW2 + 128*WS2;       // 128*WS3
    uint2* sH1 = sW3 + 128*WS3;       // 64*HS1
    uint2* sH2 = sH1 + 64*HS1;        // 64*HS2
    float* sX   = (float*)(sH2 + 64*HS2);  // 192
    float* sMax = sX + 192;                // 256

    const int t     = threadIdx.x;
    const int warp  = t >> 5;
    const int lane  = t & 31;
    const int g     = lane >> 2;
    const int tq    = lane & 3;
    const int pgrp  = warp & 1;
    const int nquad = warp >> 1;
    const int pbase = pgrp * 32;
    const int nb    = nquad * 32;
    const int slot  = blockIdx.y;

    const float* pts = (slot < 16) ? (src + (size_t)slot*NPTS*3)
                                   : (tgt + (size_t)(slot-16)*NPTS*3);

    // stage pre-split interleaved weights
    for (int i = t; i < 128*WS2; i += 256) sW2[i] = g_w2p[i];
    for (int i = t; i < 128*WS3; i += 256) sW3[i] = g_w3p[i];

    // per-thread biases for this warp's n-tiles (accumulator cols 2tq,2tq+1)
    float bias2[4][2], bias3[4][2];
    #pragma unroll
    for (int nt = 0; nt < 4; nt++) {
        bias2[nt][0] = g_b2f[nb + nt*8 + 2*tq];
        bias2[nt][1] = g_b2f[nb + nt*8 + 2*tq + 1];
        bias3[nt][0] = g_b3f[nb + nt*8 + 2*tq];
        bias3[nt][1] = g_b3f[nb + nt*8 + 2*tq + 1];
    }

    for (int st = 0; st < ENC_SUBT; st++) {
        const int p0 = (blockIdx.x * ENC_SUBT + st) * ENC_TP;
        __syncthreads();   // weights ready (st=0); prior readers of sX/sH done
        for (int i = t; i < ENC_TP*3; i += 256) sX[i] = pts[(size_t)p0*3 + i];
        __syncthreads();

        // Layer 1 (scalar): 64 pts x 32 d-pairs -> split -> interleaved H1
        for (int i = t; i < ENC_TP*32; i += 256) {
            int p = i >> 5, dp = i & 31;
            int d0 = 2*dp;
            float x = sX[p*3+0], y = sX[p*3+1], z = sX[p*3+2];
            float v0 = fmaxf(g_b1f[d0]   + x*g_w1f[d0*3+0] + y*g_w1f[d0*3+1] + z*g_w1f[d0*3+2], 0.f);
            float v1 = fmaxf(g_b1f[d0+1] + x*g_w1f[d0*3+3] + y*g_w1f[d0*3+4] + z*g_w1f[d0*3+5], 0.f);
            uint32_t ph, pm;
            pack_split(v0, v1, ph, pm);
            sH1[p*HS1 + dp] = make_uint2(ph, pm);
        }
        __syncthreads();

        // ---------------- Layer 2: K=64 (4 k16 steps) ----------------
        {
            float acc[2][4][4];
            #pragma unroll
            for (int nt = 0; nt < 4; nt++)
                #pragma unroll
                for (int mg = 0; mg < 2; mg++) {
                    acc[mg][nt][0] = bias2[nt][0]; acc[mg][nt][1] = bias2[nt][1];
                    acc[mg][nt][2] = bias2[nt][0]; acc[mg][nt][3] = bias2[nt][1];
                }
            #pragma unroll
            for (int ks = 0; ks < 4; ks++) {
                const int kp0 = ks*8;
                uint32_t ah[2][4], am[2][4];
                #pragma unroll
                for (int mg = 0; mg < 2; mg++) {
                    const uint2* r0 = sH1 + (pbase + mg*16 + g)*HS1 + kp0;
                    uint2 f0 = r0[tq];
                    uint2 f1 = r0[8*HS1 + tq];
                    uint2 f2 = r0[tq + 4];
                    uint2 f3 = r0[8*HS1 + tq + 4];
                    ah[mg][0]=f0.x; am[mg][0]=f0.y;
                    ah[mg][1]=f1.x; am[mg][1]=f1.y;
                    ah[mg][2]=f2.x; am[mg][2]=f2.y;
                    ah[mg][3]=f3.x; am[mg][3]=f3.y;
                }
                #pragma unroll
                for (int nt = 0; nt < 4; nt++) {
                    const uint2* w = sW2 + (nb + nt*8 + g)*WS2 + kp0;
                    uint2 w0 = w[tq], w1 = w[tq + 4];
                    uint32_t bh[2] = { w0.x, w1.x };
                    uint32_t bm[2] = { w0.y, w1.y };
                    #pragma unroll
                    for (int mg = 0; mg < 2; mg++) {
                        MMA_BF16(acc[mg][nt], ah[mg], bh);
                        MMA_BF16(acc[mg][nt], ah[mg], bm);
                        MMA_BF16(acc[mg][nt], am[mg], bh);
                    }
                }
            }
            // relu + split + interleaved store H2 (cols 2tq,2tq+1 = one pair)
            #pragma unroll
            for (int mg = 0; mg < 2; mg++)
                #pragma unroll
                for (int nt = 0; nt < 4; nt++) {
                    int row0 = pbase + mg*16 + g;
                    int cp   = (nb >> 1) + nt*4 + tq;    // column-pair index
                    uint32_t ph, pm;
                    pack_split(fmaxf(acc[mg][nt][0], 0.f), fmaxf(acc[mg][nt][1], 0.f), ph, pm);
                    sH2[row0*HS2 + cp] = make_uint2(ph, pm);
                    pack_split(fmaxf(acc[mg][nt][2], 0.f), fmaxf(acc[mg][nt][3], 0.f), ph, pm);
                    sH2[(row0+8)*HS2 + cp] = make_uint2(ph, pm);
                }
        }
        __syncthreads();

        // ---------------- Layer 3: K=128 (8 k16 steps) + fused max ----
        {
            float acc[2][4][4];
            #pragma unroll
            for (int nt = 0; nt < 4; nt++)
                #pragma unroll
                for (int mg = 0; mg < 2; mg++) {
                    acc[mg][nt][0] = bias3[nt][0]; acc[mg][nt][1] = bias3[nt][1];
                    acc[mg][nt][2] = bias3[nt][0]; acc[mg][nt][3] = bias3[nt][1];
                }
            #pragma unroll
            for (int ks = 0; ks < 8; ks++) {
                const int kp0 = ks*8;
                uint32_t ah[2][4], am[2][4];
                #pragma unroll
                for (int mg = 0; mg < 2; mg++) {
                    const uint2* r0 = sH2 + (pbase + mg*16 + g)*HS2 + kp0;
                    uint2 f0 = r0[tq];
                    uint2 f1 = r0[8*HS2 + tq];
                    uint2 f2 = r0[tq + 4];
                    uint2 f3 = r0[8*HS2 + tq + 4];
                    ah[mg][0]=f0.x; am[mg][0]=f0.y;
                    ah[mg][1]=f1.x; am[mg][1]=f1.y;
                    ah[mg][2]=f2.x; am[mg][2]=f2.y;
                    ah[mg][3]=f3.x; am[mg][3]=f3.y;
                }
                #pragma unroll
                for (int nt = 0; nt < 4; nt++) {
                    const uint2* w = sW3 + (nb + nt*8 + g)*WS3 + kp0;
                    uint2 w0 = w[tq], w1 = w[tq + 4];
                    uint32_t bh[2] = { w0.x, w1.x };
                    uint32_t bm[2] = { w0.y, w1.y };
                    #pragma unroll
                    for (int mg = 0; mg < 2; mg++) {
                        MMA_BF16(acc[mg][nt], ah[mg], bh);
                        MMA_BF16(acc[mg][nt], ah[mg], bm);
                        MMA_BF16(acc[mg][nt], am[mg], bh);
                    }
                }
            }
            // max over this warp's 32 rows, then over row-groups via shfl
            #pragma unroll
            for (int nt = 0; nt < 4; nt++) {
                float m0 = fmaxf(fmaxf(acc[0][nt][0], acc[0][nt][2]),
                                 fmaxf(acc[1][nt][0], acc[1][nt][2]));
                float m1 = fmaxf(fmaxf(acc[0][nt][1], acc[0][nt][3]),
                                 fmaxf(acc[1][nt][1], acc[1][nt][3]));
                #pragma unroll
                for (int o = 4; o < 32; o <<= 1) {
                    m0 = fmaxf(m0, __shfl_xor_sync(0xffffffffu, m0, o));
                    m1 = fmaxf(m1, __shfl_xor_sync(0xffffffffu, m1, o));
                }
                if (g == 0) {   // relu(max) == max(relu) (monotone)
                    sMax[pgrp*128 + nb + nt*8 + 2*tq]     = fmaxf(m0, 0.f);
                    sMax[pgrp*128 + nb + nt*8 + 2*tq + 1] = fmaxf(m1, 0.f);
                }
            }
        }
        __syncthreads();
        if (t < 128) {
            float v = fmaxf(sMax[t], sMax[128 + t]);
            atomicMax(&g_lat[slot*128 + t], __float_as_int(v)); // v >= 0
        }
    }
}

// ----------------------------------------------------------------------------
// Keypoint MLP: lat[128] -> relu(128) -> 48
// ----------------------------------------------------------------------------
__global__ void kp_kernel(const float* __restrict__ kpw1, const float* __restrict__ kpb1,
                          const float* __restrict__ kpw2, const float* __restrict__ kpb2)
{
    __shared__ float latS[128];
    __shared__ float h[128];
    int slot = blockIdx.x, t = threadIdx.x;
    latS[t] = __int_as_float(g_lat[slot*128 + t]);
    __syncthreads();
    float a = kpb1[t];
    for (int k = 0; k < 128; k++) a = fmaf(latS[k], kpw1[t*128+k], a);
    h[t] = fmaxf(a, 0.f);
    __syncthreads();
    if (t < 48) {
        float o = kpb2[t];
        for (int k = 0; k < 128; k++) o = fmaf(h[k], kpw2[t*128+k], o);
        g_kp[slot*48 + t] = o;
    }
}

// ----------------------------------------------------------------------------
// FPS: per cloud, 16 iterative argmax selections (first = vs MLP keypoints)
// jnp.argmax first-occurrence tie-break preserved (prefer smaller index).
// ----------------------------------------------------------------------------
__global__ __launch_bounds__(1024)
void fps_kernel(const float* __restrict__ src, const float* __restrict__ tgt,
                float* __restrict__ out)
{
    const int slot = blockIdx.x, t = threadIdx.x;
    const float* pts = (slot < 16) ? (src + (size_t)slot*NPTS*3)
                                   : (tgt + (size_t)(slot-16)*NPTS*3);
    float* kout = (slot < 16) ? (out + OUT_DEF + slot*48)
                              : (out + OUT_DEF + OUT_KP + (slot-16)*48);

    __shared__ float skp[48];
    __shared__ float sredV[32];
    __shared__ int   sredI[32];
    __shared__ float selS[3];
    if (t < 48) skp[t] = g_kp[slot*48 + t];

    float px[16], py[16], pz[16], mind[16];
    #pragma unroll
    for (int i = 0; i < 16; i++) {
        int n = t + i*1024;
        px[i] = pts[n*3+0]; py[i] = pts[n*3+1]; pz[i] = pts[n*3+2];
    }
    __syncthreads();

    #pragma unroll
    for (int i = 0; i < 16; i++) {
        float best = 1e30f;
        #pragma unroll
        for (int k = 0; k < 16; k++) {
            float dx = px[i]-skp[k*3+0], dy = py[i]-skp[k*3+1], dz = pz[i]-skp[k*3+2];
            best = fminf(best, dx*dx + dy*dy + dz*dz);
        }
        mind[i] = best;
    }

    for (int it = 0; it < 16; it++) {
        float bv = -1e30f; int bi = 0x7fffffff;
        #pragma unroll
        for (int i = 0; i < 16; i++) {
            if (mind[i] > bv) { bv = mind[i]; bi = t + i*1024; }
        }
        #pragma unroll
        for (int o = 16; o > 0; o >>= 1) {
            float ov = __shfl_down_sync(0xffffffffu, bv, o);
            int   oi = __shfl_down_sync(0xffffffffu, bi, o);
            if (ov > bv || (ov == bv && oi < bi)) { bv = ov; bi = oi; }
        }
        if ((t & 31) == 0) { sredV[t>>5] = bv; sredI[t>>5] = bi; }
        __syncthreads();
        if (t < 32) {
            bv = sredV[t]; bi = sredI[t];
            #pragma unroll
            for (int o = 16; o > 0; o >>= 1) {
                float ov = __shfl_down_sync(0xffffffffu, bv, o);
                int   oi = __shfl_down_sync(0xffffffffu, bi, o);
                if (ov > bv || (ov == bv && oi < bi)) { bv = ov; bi = oi; }
            }
            if (t == 0) {
                float sx = pts[bi*3+0], sy = pts[bi*3+1], sz = pts[bi*3+2];
                selS[0] = sx; selS[1] = sy; selS[2] = sz;
                kout[it*3+0] = sx; kout[it*3+1] = sy; kout[it*3+2] = sz;
                g_sel[slot*48 + it*3+0] = sx;
                g_sel[slot*48 + it*3+1] = sy;
                g_sel[slot*48 + it*3+2] = sz;
            }
        }
        __syncthreads();
        float sx = selS[0], sy = selS[1], sz = selS[2];
        #pragma unroll
        for (int i = 0; i < 16; i++) {
            float dx = px[i]-sx, dy = py[i]-sy, dz = pz[i]-sz;
            float d = dx*dx + dy*dy + dz*dz;
            mind[i] = (it == 0) ? d : fminf(mind[i], d);  // it==0: REPLACE (ref)
        }
    }
}

// ----------------------------------------------------------------------------
// Cage MLP: diff[48] -> relu(128) -> 1536; build cage = grid + disp
// ----------------------------------------------------------------------------
__global__ void cage_kernel(const float* __restrict__ cgw1, const float* __restrict__ cgb1,
                            const float* __restrict__ cgw2, const float* __restrict__ cgb2)
{
    __shared__ float diff[48];
    __shared__ float h[128];
    int b = blockIdx.x, t = threadIdx.x;
    if (t < 48) diff[t] = g_sel[(16+b)*48 + t] - g_sel[b*48 + t];
    __syncthreads();
    float a = cgb1[t];
    for (int k = 0; k < 48; k++) a = fmaf(diff[k], cgw1[t*48+k], a);
    h[t] = fmaxf(a, 0.f);
    __syncthreads();
    for (int o = t; o < 1536; o += 128) {
        float acc = cgb2[o];
        for (int k = 0; k < 128; k++) acc = fmaf(h[k], cgw2[o*128+k], acc);
        int c = o % 3, cell = o / 3;
        int i = cell >> 6, j = (cell >> 3) & 7, kz = cell & 7;
        int li = (c == 0) ? i : (c == 1) ? j : kz;
        g_cage[b*1536 + o] = (float)li * (1.0f/7.0f) + acc;
    }
}

// ----------------------------------------------------------------------------
// Per-batch min/max of source points
// ----------------------------------------------------------------------------
__global__ __launch_bounds__(1024)
void pmm_kernel(const float* __restrict__ src)
{
    int b = blockIdx.x, t = threadIdx.x;
    const float* p = src + (size_t)b*NPTS*3;
    float mn0=1e30f, mn1=1e30f, mn2=1e30f, mx0=-1e30f, mx1=-1e30f, mx2=-1e30f;
    for (int n = t; n < NPTS; n += 1024) {
        float x = p[n*3+0], y = p[n*3+1], z = p[n*3+2];
        mn0 = fminf(mn0,x); mx0 = fmaxf(mx0,x);
        mn1 = fminf(mn1,y); mx1 = fmaxf(mx1,y);
        mn2 = fminf(mn2,z); mx2 = fmaxf(mx2,z);
    }
    #pragma unroll
    for (int o = 16; o > 0; o >>= 1) {
        mn0 = fminf(mn0, __shfl_down_sync(0xffffffffu, mn0, o));
        mn1 = fminf(mn1, __shfl_down_sync(0xffffffffu, mn1, o));
        mn2 = fminf(mn2, __shfl_down_sync(0xffffffffu, mn2, o));
        mx0 = fmaxf(mx0, __shfl_down_sync(0xffffffffu, mx0, o));
        mx1 = fmaxf(mx1, __shfl_down_sync(0xffffffffu, mx1, o));
        mx2 = fmaxf(mx2, __shfl_down_sync(0xffffffffu, mx2, o));
    }
    __shared__ float s[32][6];
    if ((t & 31) == 0) {
        s[t>>5][0]=mn0; s[t>>5][1]=mn1; s[t>>5][2]=mn2;
        s[t>>5][3]=mx0; s[t>>5][4]=mx1; s[t>>5][5]=mx2;
    }
    __syncthreads();
    if (t < 32) {
        mn0=s[t][0]; mn1=s[t][1]; mn2=s[t][2]; mx0=s[t][3]; mx1=s[t][4]; mx2=s[t][5];
        #pragma unroll
        for (int o = 16; o > 0; o >>= 1) {
            mn0 = fminf(mn0, __shfl_down_sync(0xffffffffu, mn0, o));
            mn1 = fminf(mn1, __shfl_down_sync(0xffffffffu, mn1, o));
            mn2 = fminf(mn2, __shfl_down_sync(0xffffffffu, mn2, o));
            mx0 = fmaxf(mx0, __shfl_down_sync(0xffffffffu, mx0, o));
            mx1 = fmaxf(mx1, __shfl_down_sync(0xffffffffu, mx1, o));
            mx2 = fmaxf(mx2, __shfl_down_sync(0xffffffffu, mx2, o));
        }
        if (t == 0) {
            g_pmm[b*6+0]=mn0; g_pmm[b*6+1]=mn1; g_pmm[b*6+2]=mn2;
            g_pmm[b*6+3]=mx0; g_pmm[b*6+4]=mx1; g_pmm[b*6+5]=mx2;
        }
    }
}

// ----------------------------------------------------------------------------
// Trilinear cage deform
// ----------------------------------------------------------------------------
__global__ void deform_kernel(const float* __restrict__ src, float* __restrict__ out)
{
    int b = blockIdx.y, t = threadIdx.x;
    __shared__ float cg[1536];
    __shared__ float pm[6];
    for (int i = t; i < 1536; i += 256) cg[i] = g_cage[b*1536 + i];
    if (t < 6) pm[t] = g_pmm[b*6 + t];
    __syncthreads();

    int n = blockIdx.x*256 + t;
    const float* p = src + ((size_t)b*NPTS + n)*3;
    float x = p[0], y = p[1], z = p[2];
    float tx = (x - pm[0]) / (pm[3]-pm[0] + 1e-6f) * 7.f;
    float ty = (y - pm[1]) / (pm[4]-pm[1] + 1e-6f) * 7.f;
    float tz = (z - pm[2]) / (pm[5]-pm[2] + 1e-6f) * 7.f;
    int u = min(max((int)tx, 0), 6);
    int v = min(max((int)ty, 0), 6);
    int w = min(max((int)tz, 0), 6);
    float wx = tx - (float)u, wy = ty - (float)v, wz = tz - (float)w;
    float ax = 1.f-wx, ay = 1.f-wy, az = 1.f-wz;

    int base = u*64 + v*8 + w;
    const float* c000 = &cg[(base     )*3];
    const float* c100 = &cg[(base + 64)*3];
    const float* c010 = &cg[(base +  8)*3];
    const float* c110 = &cg[(base + 72)*3];
    const float* c001 = &cg[(base +  1)*3];
    const float* c101 = &cg[(base + 65)*3];
    const float* c011 = &cg[(base +  9)*3];
    const float* c111 = &cg[(base + 73)*3];

    float w000 = ax*ay*az, w100 = wx*ay*az, w010 = ax*wy*az, w110 = wx*wy*az;
    float w001 = ax*ay*wz, w101 = wx*ay*wz, w011 = ax*wy*wz, w111 = wx*wy*wz;

    #pragma unroll
    for (int c = 0; c < 3; c++) {
        float d = w000*c000[c] + w100*c100[c] + w010*c010[c] + w110*c110[c]
                + w001*c001[c] + w101*c101[c] + w011*c011[c] + w111*c111[c];
        out[((size_t)b*NPTS + n)*3 + c] = p[c] + d;
    }
}

// ----------------------------------------------------------------------------
// Launch
// ----------------------------------------------------------------------------
extern "C" void kernel_launch(void* const* d_in, const int* in_sizes, int n_in,
                              void* d_out, int out_size)
{
    const float* src  = (const float*)d_in[0];
    const float* tgt  = (const float*)d_in[1];
    const float* ew1  = (const float*)d_in[2];
    const float* eb1  = (const float*)d_in[3];
    const float* g1   = (const float*)d_in[4];
    const float* be1  = (const float*)d_in[5];
    const float* m1   = (const float*)d_in[6];
    const float* v1   = (const float*)d_in[7];
    const float* ew2  = (const float*)d_in[8];
    const float* eb2  = (const float*)d_in[9];
    const float* g2   = (const float*)d_in[10];
    const float* be2  = (const float*)d_in[11];
    const float* m2   = (const float*)d_in[12];
    const float* v2   = (const float*)d_in[13];
    const float* ew3  = (const float*)d_in[14];
    const float* eb3  = (const float*)d_in[15];
    const float* g3   = (const float*)d_in[16];
    const float* be3  = (const float*)d_in[17];
    const float* m3   = (const float*)d_in[18];
    const float* v3   = (const float*)d_in[19];
    const float* kpw1 = (const float*)d_in[20];
    const float* kpb1 = (const float*)d_in[21];
    const float* kpw2 = (const float*)d_in[22];
    const float* kpb2 = (const float*)d_in[23];
    const float* cgw1 = (const float*)d_in[24];
    const float* cgb1 = (const float*)d_in[25];
    const float* cgw2 = (const float*)d_in[26];
    const float* cgb2 = (const float*)d_in[27];
    float* out = (float*)d_out;

    cudaFuncSetAttribute(enc_kernel, cudaFuncAttributeMaxDynamicSharedMemorySize,
                         ENC_SMEM_BYTES);

    prep_kernel<<<1, 256>>>(ew1, eb1, g1, be1, m1, v1,
                            ew2, eb2, g2, be2, m2, v2,
                            ew3, eb3, g3, be3, m3, v3);
    enc_kernel<<<dim3(NPTS/(ENC_TP*ENC_SUBT), NSLOT), 256, ENC_SMEM_BYTES>>>(src, tgt);
    kp_kernel<<<NSLOT, 128>>>(kpw1, kpb1, kpw2, kpb2);
    fps_kernel<<<NSLOT, 1024>>>(src, tgt, out);
    cage_kernel<<<NB, 128>>>(cgw1, cgb1, cgw2, cgb2);
    pmm_kernel<<<NB, 1024>>>(src);
    deform_kernel<<<dim3(NPTS/256, NB), 256>>>(src, out);
}

// round 10
// speedup vs baseline: 1.1723x; 1.1723x over previous
#include <cuda_runtime.h>
#include <cuda_bf16.h>
#include <math.h>
#include <cstdint>

#define NPTS   16384
#define NB     16
#define NSLOT  32          // 16 source + 16 target clouds
#define KKP    16
#define OUT_DEF (NB*NPTS*3)   // 786432
#define OUT_KP  (NB*KKP*3)    // 768
#define BN_EPS 1e-5f

// ----------------------------------------------------------------------------
// bf16 2-way split: v = h + m + r, |r| <= ~2^-18 |v|
// ----------------------------------------------------------------------------
__device__ __forceinline__ void bsplit2(float v, unsigned short &h, unsigned short &m) {
    __nv_bfloat16 bh = __float2bfloat16(v);
    float r = v - __bfloat162float(bh);
    __nv_bfloat16 bm = __float2bfloat16(r);
    h = __bfloat16_as_ushort(bh);
    m = __bfloat16_as_ushort(bm);
}
__device__ __forceinline__ void pack_split(float v0, float v1, uint32_t &ph, uint32_t &pm) {
    unsigned short h0, m0, h1, m1;
    bsplit2(v0, h0, m0); bsplit2(v1, h1, m1);
    ph = (uint32_t)h0 | ((uint32_t)h1 << 16);
    pm = (uint32_t)m0 | ((uint32_t)m1 << 16);
}

// bf16 m16n8k16 MMA, fp32 accumulate (baseline PTX, works on compute_103)
#define MMA_BF16(acc, A, B) \
    asm volatile("mma.sync.aligned.m16n8k16.row.col.f32.bf16.bf16.f32 " \
        "{%0,%1,%2,%3}, {%4,%5,%6,%7}, {%8,%9}, {%0,%1,%2,%3};" \
        : "+f"((acc)[0]), "+f"((acc)[1]), "+f"((acc)[2]), "+f"((acc)[3]) \
        : "r"((A)[0]), "r"((A)[1]), "r"((A)[2]), "r"((A)[3]), \
          "r"((B)[0]), "r"((B)[1]))

// ----------------------------------------------------------------------------
// Device scratch (no allocations allowed)
// ----------------------------------------------------------------------------
#define WS2 36   // W2 kpair stride (32 pairs + pad); banks 4g+tq conflict-free
#define WS3 68   // W3 kpair stride (64 pairs + pad)
#define HS1 36   // H1 kpair stride
#define HS2 68   // H2 kpair stride

__device__ float    g_w1f[64*3];
__device__ float    g_b1f[64];
__device__ uint32_t g_w2h[128*WS2];  // W2 split-hi, packed bf16x2 [n][kpair]
__device__ uint32_t g_w2m[128*WS2];  // W2 split-lo
__device__ float    g_b2f[128];
__device__ uint32_t g_w3h[128*WS3];
__device__ uint32_t g_w3m[128*WS3];
__device__ float    g_b3f[128];
__device__ int      g_lat[NSLOT*128];  // latent max (float bits; relu => >=0)
__device__ float    g_kp[NSLOT*48];
__device__ float    g_sel[NSLOT*48];
__device__ float    g_cage[NB*1536];
__device__ float    g_pmm[NB*6];
__device__ float    g_mind[NSLOT*NPTS]; // FPS initial min-dist (2 MB)

// ----------------------------------------------------------------------------
// Prep: fold BN into weights, 2-way bf16 split, pack k-pairs; zero latents
// ----------------------------------------------------------------------------
__global__ void prep_kernel(
    const float* w1, const float* b1, const float* g1, const float* be1,
    const float* m1, const float* v1,
    const float* w2, const float* b2, const float* g2, const float* be2,
    const float* m2, const float* v2,
    const float* w3, const float* b3, const float* g3, const float* be3,
    const float* m3, const float* v3)
{
    int t = threadIdx.x;
    for (int d = t; d < 64; d += 256) {
        float s = g1[d] * rsqrtf(v1[d] + BN_EPS);
        g_w1f[d*3+0] = w1[d*3+0]*s;
        g_w1f[d*3+1] = w1[d*3+1]*s;
        g_w1f[d*3+2] = w1[d*3+2]*s;
        g_b1f[d] = (b1[d]-m1[d])*s + be1[d];
    }
    for (int d = t; d < 128; d += 256) {
        float s2 = g2[d] * rsqrtf(v2[d] + BN_EPS);
        for (int k = 0; k < 64; k += 2) {
            uint32_t ph, pm;
            pack_split(w2[d*64+k]*s2, w2[d*64+k+1]*s2, ph, pm);
            g_w2h[d*WS2 + (k>>1)] = ph;
            g_w2m[d*WS2 + (k>>1)] = pm;
        }
        g_b2f[d] = (b2[d]-m2[d])*s2 + be2[d];
        float s3 = g3[d] * rsqrtf(v3[d] + BN_EPS);
        for (int k = 0; k < 128; k += 2) {
            uint32_t ph, pm;
            pack_split(w3[d*128+k]*s3, w3[d*128+k+1]*s3, ph, pm);
            g_w3h[d*WS3 + (k>>1)] = ph;
            g_w3m[d*WS3 + (k>>1)] = pm;
        }
        g_b3f[d] = (b3[d]-m3[d])*s3 + be3[d];
    }
    for (int i = t; i < NSLOT*128; i += 256) g_lat[i] = 0;
}

// ----------------------------------------------------------------------------
// Encoder: 3->64->128->128 MLP + segmented max, layers 2/3 on bf16 m16n8k16
// mma.sync, 2-way split, 3 terms (hh+hm+mh; ~1e-5 rel; only affects 32
// first-iteration FPS argmax decisions; validated across R7/R8).
// 512 threads (16 warps, 4/SMSP for latency hiding), subtile = 128 points.
// Warp (pgrp = w&3, nquad = w>>2) owns 32 pts x 32 dims; identical warp-level
// arithmetic / fragment layout / strides as the 475us R7 kernel (LDS.32,
// separate h/m arrays -- the uint2 LDS.64 variant regressed: crossbar-bound).
// Smem ~216.6 KB: 1 CTA/SM but 2x eligible warps per scheduler vs R7.
// ----------------------------------------------------------------------------
#define ENC_TP   128
#define ENC_SUBT 4
#define ENC_THREADS 512
#define ENC_SMEM_U32 (2*128*WS2 + 2*128*WS3 + 2*128*HS1 + 2*128*HS2 + 384 + 512)
#define ENC_SMEM_BYTES (ENC_SMEM_U32*4)

extern __shared__ uint32_t enc_smem[];

__global__ __launch_bounds__(ENC_THREADS, 1)
void enc_kernel(const float* __restrict__ src, const float* __restrict__ tgt)
{
    uint32_t* sW2h = enc_smem;               // 128*WS2
    uint32_t* sW2m = sW2h + 128*WS2;
    uint32_t* sW3h = sW2m + 128*WS2;         // 128*WS3
    uint32_t* sW3m = sW3h + 128*WS3;
    uint32_t* sH1h = sW3m + 128*WS3;         // 128*HS1
    uint32_t* sH1m = sH1h + 128*HS1;
    uint32_t* sH2h = sH1m + 128*HS1;         // 128*HS2
    uint32_t* sH2m = sH2h + 128*HS2;
    float*    sX   = (float*)(sH2m + 128*HS2); // 384
    float*    sMax = sX + 384;                 // 512 (4 pgrp x 128)

    const int t     = threadIdx.x;
    const int warp  = t >> 5;
    const int lane  = t & 31;
    const int g     = lane >> 2;
    const int tq    = lane & 3;
    const int pgrp  = warp & 3;              // 0..3 -> point rows 32*pgrp..+31
    const int nquad = warp >> 2;             // 0..3 -> dim cols 32*nquad..+31
    const int pbase = pgrp * 32;
    const int nb    = nquad * 32;
    const int slot  = blockIdx.y;

    const float* pts = (slot < 16) ? (src + (size_t)slot*NPTS*3)
                                   : (tgt + (size_t)(slot-16)*NPTS*3);

    // stage pre-split weights
    for (int i = t; i < 128*WS2; i += ENC_THREADS) { sW2h[i] = g_w2h[i]; sW2m[i] = g_w2m[i]; }
    for (int i = t; i < 128*WS3; i += ENC_THREADS) { sW3h[i] = g_w3h[i]; sW3m[i] = g_w3m[i]; }

    // per-thread biases for this warp's n-tiles (accumulator cols 2tq,2tq+1)
    float bias2[4][2], bias3[4][2];
    #pragma unroll
    for (int nt = 0; nt < 4; nt++) {
        bias2[nt][0] = g_b2f[nb + nt*8 + 2*tq];
        bias2[nt][1] = g_b2f[nb + nt*8 + 2*tq + 1];
        bias3[nt][0] = g_b3f[nb + nt*8 + 2*tq];
        bias3[nt][1] = g_b3f[nb + nt*8 + 2*tq + 1];
    }

    float gmax = 0.f;

    for (int st = 0; st < ENC_SUBT; st++) {
        const int p0 = (blockIdx.x * ENC_SUBT + st) * ENC_TP;
        __syncthreads();   // weights ready (st=0); prior readers of sX/sH/sMax done
        for (int i = t; i < ENC_TP*3; i += ENC_THREADS) sX[i] = pts[(size_t)p0*3 + i];
        __syncthreads();

        // Layer 1 (scalar): 128 pts x 32 d-pairs -> split -> packed H1
        for (int i = t; i < ENC_TP*32; i += ENC_THREADS) {
            int p = i >> 5, dp = i & 31;
            int d0 = 2*dp;
            float x = sX[p*3+0], y = sX[p*3+1], z = sX[p*3+2];
            float v0 = fmaxf(g_b1f[d0]   + x*g_w1f[d0*3+0] + y*g_w1f[d0*3+1] + z*g_w1f[d0*3+2], 0.f);
            float v1 = fmaxf(g_b1f[d0+1] + x*g_w1f[d0*3+3] + y*g_w1f[d0*3+4] + z*g_w1f[d0*3+5], 0.f);
            uint32_t ph, pm;
            pack_split(v0, v1, ph, pm);
            sH1h[p*HS1 + dp] = ph;
            sH1m[p*HS1 + dp] = pm;
        }
        __syncthreads();

        // ---------------- Layer 2: K=64 (4 k16 steps) ----------------
        {
            float acc[2][4][4];
            #pragma unroll
            for (int nt = 0; nt < 4; nt++)
                #pragma unroll
                for (int mg = 0; mg < 2; mg++) {
                    acc[mg][nt][0] = bias2[nt][0]; acc[mg][nt][1] = bias2[nt][1];
                    acc[mg][nt][2] = bias2[nt][0]; acc[mg][nt][3] = bias2[nt][1];
                }
            #pragma unroll
            for (int ks = 0; ks < 4; ks++) {
                const int kp0 = ks*8;
                uint32_t ah[2][4], am[2][4];
                #pragma unroll
                for (int mg = 0; mg < 2; mg++) {
                    const uint32_t* r0h = sH1h + (pbase + mg*16 + g)*HS1 + kp0;
                    const uint32_t* r0m = sH1m + (pbase + mg*16 + g)*HS1 + kp0;
                    ah[mg][0] = r0h[tq];            am[mg][0] = r0m[tq];
                    ah[mg][1] = r0h[8*HS1 + tq];    am[mg][1] = r0m[8*HS1 + tq];
                    ah[mg][2] = r0h[tq + 4];        am[mg][2] = r0m[tq + 4];
                    ah[mg][3] = r0h[8*HS1 + tq+4];  am[mg][3] = r0m[8*HS1 + tq+4];
                }
                #pragma unroll
                for (int nt = 0; nt < 4; nt++) {
                    const uint32_t* wh = sW2h + (nb + nt*8 + g)*WS2 + kp0;
                    const uint32_t* wm = sW2m + (nb + nt*8 + g)*WS2 + kp0;
                    uint32_t bh[2] = { wh[tq], wh[tq+4] };
                    uint32_t bm[2] = { wm[tq], wm[tq+4] };
                    #pragma unroll
                    for (int mg = 0; mg < 2; mg++) {
                        MMA_BF16(acc[mg][nt], ah[mg], bh);
                        MMA_BF16(acc[mg][nt], ah[mg], bm);
                        MMA_BF16(acc[mg][nt], am[mg], bh);
                    }
                }
            }
            // relu + split + packed store H2 (cols 2tq,2tq+1 form one pair)
            #pragma unroll
            for (int mg = 0; mg < 2; mg++)
                #pragma unroll
                for (int nt = 0; nt < 4; nt++) {
                    int row0 = pbase + mg*16 + g;
                    int cp   = (nb >> 1) + nt*4 + tq;    // column-pair index
                    uint32_t ph, pm;
                    pack_split(fmaxf(acc[mg][nt][0], 0.f), fmaxf(acc[mg][nt][1], 0.f), ph, pm);
                    sH2h[row0*HS2 + cp] = ph;
                    sH2m[row0*HS2 + cp] = pm;
                    pack_split(fmaxf(acc[mg][nt][2], 0.f), fmaxf(acc[mg][nt][3], 0.f), ph, pm);
                    sH2h[(row0+8)*HS2 + cp] = ph;
                    sH2m[(row0+8)*HS2 + cp] = pm;
                }
        }
        __syncthreads();

        // ---------------- Layer 3: K=128 (8 k16 steps) + fused max ----
        {
            float acc[2][4][4];
            #pragma unroll
            for (int nt = 0; nt < 4; nt++)
                #pragma unroll
                for (int mg = 0; mg < 2; mg++) {
                    acc[mg][nt][0] = bias3[nt][0]; acc[mg][nt][1] = bias3[nt][1];
                    acc[mg][nt][2] = bias3[nt][0]; acc[mg][nt][3] = bias3[nt][1];
                }
            #pragma unroll
            for (int ks = 0; ks < 8; ks++) {
                const int kp0 = ks*8;
                uint32_t ah[2][4], am[2][4];
                #pragma unroll
                for (int mg = 0; mg < 2; mg++) {
                    const uint32_t* r0h = sH2h + (pbase + mg*16 + g)*HS2 + kp0;
                    const uint32_t* r0m = sH2m + (pbase + mg*16 + g)*HS2 + kp0;
                    ah[mg][0] = r0h[tq];            am[mg][0] = r0m[tq];
                    ah[mg][1] = r0h[8*HS2 + tq];    am[mg][1] = r0m[8*HS2 + tq];
                    ah[mg][2] = r0h[tq + 4];        am[mg][2] = r0m[tq + 4];
                    ah[mg][3] = r0h[8*HS2 + tq+4];  am[mg][3] = r0m[8*HS2 + tq+4];
                }
                #pragma unroll
                for (int nt = 0; nt < 4; nt++) {
                    const uint32_t* wh = sW3h + (nb + nt*8 + g)*WS3 + kp0;
                    const uint32_t* wm = sW3m + (nb + nt*8 + g)*WS3 + kp0;
                    uint32_t bh[2] = { wh[tq], wh[tq+4] };
                    uint32_t bm[2] = { wm[tq], wm[tq+4] };
                    #pragma unroll
                    for (int mg = 0; mg < 2; mg++) {
                        MMA_BF16(acc[mg][nt], ah[mg], bh);
                        MMA_BF16(acc[mg][nt], ah[mg], bm);
                        MMA_BF16(acc[mg][nt], am[mg], bh);
                    }
                }
            }
            // max over this warp's 32 rows, then across lanes via shfl
            #pragma unroll
            for (int nt = 0; nt < 4; nt++) {
                float m0 = fmaxf(fmaxf(acc[0][nt][0], acc[0][nt][2]),
                                 fmaxf(acc[1][nt][0], acc[1][nt][2]));
                float m1 = fmaxf(fmaxf(acc[0][nt][1], acc[0][nt][3]),
                                 fmaxf(acc[1][nt][1], acc[1][nt][3]));
                #pragma unroll
                for (int o = 4; o < 32; o <<= 1) {
                    m0 = fmaxf(m0, __shfl_xor_sync(0xffffffffu, m0, o));
                    m1 = fmaxf(m1, __shfl_xor_sync(0xffffffffu, m1, o));
                }
                if (g == 0) {   // relu(max) == max(relu) (monotone)
                    sMax[pgrp*128 + nb + nt*8 + 2*tq]     = fmaxf(m0, 0.f);
                    sMax[pgrp*128 + nb + nt*8 + 2*tq + 1] = fmaxf(m1, 0.f);
                }
            }
        }
        __syncthreads();
        if (t < 128) {
            float v = fmaxf(fmaxf(sMax[t], sMax[128 + t]),
                            fmaxf(sMax[256 + t], sMax[384 + t]));
            gmax = fmaxf(gmax, v);
        }
    }
    if (t < 128)
        atomicMax(&g_lat[slot*128 + t], __float_as_int(gmax)); // gmax >= 0
}

// ----------------------------------------------------------------------------
// Keypoint MLP: lat[128] -> relu(128) -> 48
// ----------------------------------------------------------------------------
__global__ void kp_kernel(const float* __restrict__ kpw1, const float* __restrict__ kpb1,
                          const float* __restrict__ kpw2, const float* __restrict__ kpb2)
{
    __shared__ float latS[128];
    __shared__ float h[128];
    int slot = blockIdx.x, t = threadIdx.x;
    latS[t] = __int_as_float(g_lat[slot*128 + t]);
    __syncthreads();
    float a = kpb1[t];
    for (int k = 0; k < 128; k++) a = fmaf(latS[k], kpw1[t*128+k], a);
    h[t] = fmaxf(a, 0.f);
    __syncthreads();
    if (t < 48) {
        float o = kpb2[t];
        for (int k = 0; k < 128; k++) o = fmaf(h[k], kpw2[t*128+k], o);
        g_kp[slot*48 + t] = o;
    }
}

// ----------------------------------------------------------------------------
// FPS init: d0 = min dist to 16 MLP keypoints, spread over 128 blocks
// (identical expression order to the in-fps version -> same rounding).
// ----------------------------------------------------------------------------
__global__ __launch_bounds__(1024)
void fps_init_kernel(const float* __restrict__ src, const float* __restrict__ tgt)
{
    const int chunk = blockIdx.x, slot = blockIdx.y, t = threadIdx.x;
    const float* pts = (slot < 16) ? (src + (size_t)slot*NPTS*3)
                                   : (tgt + (size_t)(slot-16)*NPTS*3);
    __shared__ float skp[48];
    if (t < 48) skp[t] = g_kp[slot*48 + t];
    __syncthreads();

    const int base = chunk * 4096;
    #pragma unroll
    for (int i = 0; i < 4; i++) {
        int n = base + i*1024 + t;
        float px = pts[n*3+0], py = pts[n*3+1], pz = pts[n*3+2];
        float best = 1e30f;
        #pragma unroll
        for (int k = 0; k < 16; k++) {
            float dx = px-skp[k*3+0], dy = py-skp[k*3+1], dz = pz-skp[k*3+2];
            best = fminf(best, dx*dx + dy*dy + dz*dz);
        }
        g_mind[slot*NPTS + n] = best;
    }
}

// ----------------------------------------------------------------------------
// FPS: per cloud, 16 iterative argmax selections.
// jnp.argmax first-occurrence tie-break preserved (prefer smaller index).
// ----------------------------------------------------------------------------
__global__ __launch_bounds__(1024)
void fps_kernel(const float* __restrict__ src, const float* __restrict__ tgt,
                float* __restrict__ out)
{
    const int slot = blockIdx.x, t = threadIdx.x;
    const float* pts = (slot < 16) ? (src + (size_t)slot*NPTS*3)
                                   : (tgt + (size_t)(slot-16)*NPTS*3);
    float* kout = (slot < 16) ? (out + OUT_DEF + slot*48)
                              : (out + OUT_DEF + OUT_KP + (slot-16)*48);

    __shared__ float sredV[32];
    __shared__ int   sredI[32];
    __shared__ float selS[3];

    float px[16], py[16], pz[16], mind[16];
    #pragma unroll
    for (int i = 0; i < 16; i++) {
        int n = t + i*1024;
        px[i] = pts[n*3+0]; py[i] = pts[n*3+1]; pz[i] = pts[n*3+2];
        mind[i] = g_mind[slot*NPTS + n];
    }

    for (int it = 0; it < 16; it++) {
        float bv = -1e30f; int bi = 0x7fffffff;
        #pragma unroll
        for (int i = 0; i < 16; i++) {
            if (mind[i] > bv) { bv = mind[i]; bi = t + i*1024; }
        }
        #pragma unroll
        for (int o = 16; o > 0; o >>= 1) {
            float ov = __shfl_down_sync(0xffffffffu, bv, o);
            int   oi = __shfl_down_sync(0xffffffffu, bi, o);
            if (ov > bv || (ov == bv && oi < bi)) { bv = ov; bi = oi; }
        }
        if ((t & 31) == 0) { sredV[t>>5] = bv; sredI[t>>5] = bi; }
        __syncthreads();
        if (t < 32) {
            bv = sredV[t]; bi = sredI[t];
            #pragma unroll
            for (int o = 16; o > 0; o >>= 1) {
                float ov = __shfl_down_sync(0xffffffffu, bv, o);
                int   oi = __shfl_down_sync(0xffffffffu, bi, o);
                if (ov > bv || (ov == bv && oi < bi)) { bv = ov; bi = oi; }
            }
            if (t == 0) {
                float sx = pts[bi*3+0], sy = pts[bi*3+1], sz = pts[bi*3+2];
                selS[0] = sx; selS[1] = sy; selS[2] = sz;
                kout[it*3+0] = sx; kout[it*3+1] = sy; kout[it*3+2] = sz;
                g_sel[slot*48 + it*3+0] = sx;
                g_sel[slot*48 + it*3+1] = sy;
                g_sel[slot*48 + it*3+2] = sz;
            }
        }
        __syncthreads();
        float sx = selS[0], sy = selS[1], sz = selS[2];
        #pragma unroll
        for (int i = 0; i < 16; i++) {
            float dx = px[i]-sx, dy = py[i]-sy, dz = pz[i]-sz;
            float d = dx*dx + dy*dy + dz*dz;
            mind[i] = (it == 0) ? d : fminf(mind[i], d);  // it==0: REPLACE (ref)
        }
    }
}

// ----------------------------------------------------------------------------
// Cage MLP: diff[48] -> relu(128) -> 1536; build cage = grid + disp
// ----------------------------------------------------------------------------
__global__ void cage_kernel(const float* __restrict__ cgw1, const float* __restrict__ cgb1,
                            const float* __restrict__ cgw2, const float* __restrict__ cgb2)
{
    __shared__ float diff[48];
    __shared__ float h[128];
    int b = blockIdx.x, t = threadIdx.x;
    if (t < 48) diff[t] = g_sel[(16+b)*48 + t] - g_sel[b*48 + t];
    __syncthreads();
    float a = cgb1[t];
    for (int k = 0; k < 48; k++) a = fmaf(diff[k], cgw1[t*48+k], a);
    h[t] = fmaxf(a, 0.f);
    __syncthreads();
    for (int o = t; o < 1536; o += 128) {
        float acc = cgb2[o];
        for (int k = 0; k < 128; k++) acc = fmaf(h[k], cgw2[o*128+k], acc);
        int c = o % 3, cell = o / 3;
        int i = cell >> 6, j = (cell >> 3) & 7, kz = cell & 7;
        int li = (c == 0) ? i : (c == 1) ? j : kz;
        g_cage[b*1536 + o] = (float)li * (1.0f/7.0f) + acc;
    }
}

// ----------------------------------------------------------------------------
// Per-batch min/max of source points
// ----------------------------------------------------------------------------
__global__ __launch_bounds__(1024)
void pmm_kernel(const float* __restrict__ src)
{
    int b = blockIdx.x, t = threadIdx.x;
    const float* p = src + (size_t)b*NPTS*3;
    float mn0=1e30f, mn1=1e30f, mn2=1e30f, mx0=-1e30f, mx1=-1e30f, mx2=-1e30f;
    for (int n = t; n < NPTS; n += 1024) {
        float x = p[n*3+0], y = p[n*3+1], z = p[n*3+2];
        mn0 = fminf(mn0,x); mx0 = fmaxf(mx0,x);
        mn1 = fminf(mn1,y); mx1 = fmaxf(mx1,y);
        mn2 = fminf(mn2,z); mx2 = fmaxf(mx2,z);
    }
    #pragma unroll
    for (int o = 16; o > 0; o >>= 1) {
        mn0 = fminf(mn0, __shfl_down_sync(0xffffffffu, mn0, o));
        mn1 = fminf(mn1, __shfl_down_sync(0xffffffffu, mn1, o));
        mn2 = fminf(mn2, __shfl_down_sync(0xffffffffu, mn2, o));
        mx0 = fmaxf(mx0, __shfl_down_sync(0xffffffffu, mx0, o));
        mx1 = fmaxf(mx1, __shfl_down_sync(0xffffffffu, mx1, o));
        mx2 = fmaxf(mx2, __shfl_down_sync(0xffffffffu, mx2, o));
    }
    __shared__ float s[32][6];
    if ((t & 31) == 0) {
        s[t>>5][0]=mn0; s[t>>5][1]=mn1; s[t>>5][2]=mn2;
        s[t>>5][3]=mx0; s[t>>5][4]=mx1; s[t>>5][5]=mx2;
    }
    __syncthreads();
    if (t < 32) {
        mn0=s[t][0]; mn1=s[t][1]; mn2=s[t][2]; mx0=s[t][3]; mx1=s[t][4]; mx2=s[t][5];
        #pragma unroll
        for (int o = 16; o > 0; o >>= 1) {
            mn0 = fminf(mn0, __shfl_down_sync(0xffffffffu, mn0, o));
            mn1 = fminf(mn1, __shfl_down_sync(0xffffffffu, mn1, o));
            mn2 = fminf(mn2, __shfl_down_sync(0xffffffffu, mn2, o));
            mx0 = fmaxf(mx0, __shfl_down_sync(0xffffffffu, mx0, o));
            mx1 = fmaxf(mx1, __shfl_down_sync(0xffffffffu, mx1, o));
            mx2 = fmaxf(mx2, __shfl_down_sync(0xffffffffu, mx2, o));
        }
        if (t == 0) {
            g_pmm[b*6+0]=mn0; g_pmm[b*6+1]=mn1; g_pmm[b*6+2]=mn2;
            g_pmm[b*6+3]=mx0; g_pmm[b*6+4]=mx1; g_pmm[b*6+5]=mx2;
        }
    }
}

// ----------------------------------------------------------------------------
// Trilinear cage deform
// ----------------------------------------------------------------------------
__global__ void deform_kernel(const float* __restrict__ src, float* __restrict__ out)
{
    int b = blockIdx.y, t = threadIdx.x;
    __shared__ float cg[1536];
    __shared__ float pm[6];
    for (int i = t; i < 1536; i += 256) cg[i] = g_cage[b*1536 + i];
    if (t < 6) pm[t] = g_pmm[b*6 + t];
    __syncthreads();

    int n = blockIdx.x*256 + t;
    const float* p = src + ((size_t)b*NPTS + n)*3;
    float x = p[0], y = p[1], z = p[2];
    float tx = (x - pm[0]) / (pm[3]-pm[0] + 1e-6f) * 7.f;
    float ty = (y - pm[1]) / (pm[4]-pm[1] + 1e-6f) * 7.f;
    float tz = (z - pm[2]) / (pm[5]-pm[2] + 1e-6f) * 7.f;
    int u = min(max((int)tx, 0), 6);
    int v = min(max((int)ty, 0), 6);
    int w = min(max((int)tz, 0), 6);
    float wx = tx - (float)u, wy = ty - (float)v, wz = tz - (float)w;
    float ax = 1.f-wx, ay = 1.f-wy, az = 1.f-wz;

    int base = u*64 + v*8 + w;
    const float* c000 = &cg[(base     )*3];
    const float* c100 = &cg[(base + 64)*3];
    const float* c010 = &cg[(base +  8)*3];
    const float* c110 = &cg[(base + 72)*3];
    const float* c001 = &cg[(base +  1)*3];
    const float* c101 = &cg[(base + 65)*3];
    const float* c011 = &cg[(base +  9)*3];
    const float* c111 = &cg[(base + 73)*3];

    float w000 = ax*ay*az, w100 = wx*ay*az, w010 = ax*wy*az, w110 = wx*wy*az;
    float w001 = ax*ay*wz, w101 = wx*ay*wz, w011 = ax*wy*wz, w111 = wx*wy*wz;

    #pragma unroll
    for (int c = 0; c < 3; c++) {
        float d = w000*c000[c] + w100*c100[c] + w010*c010[c] + w110*c110[c]
                + w001*c001[c] + w101*c101[c] + w011*c011[c] + w111*c111[c];
        out[((size_t)b*NPTS + n)*3 + c] = p[c] + d;
    }
}

// ----------------------------------------------------------------------------
// Launch
// ----------------------------------------------------------------------------
extern "C" void kernel_launch(void* const* d_in, const int* in_sizes, int n_in,
                              void* d_out, int out_size)
{
    const float* src  = (const float*)d_in[0];
    const float* tgt  = (const float*)d_in[1];
    const float* ew1  = (const float*)d_in[2];
    const float* eb1  = (const float*)d_in[3];
    const float* g1   = (const float*)d_in[4];
    const float* be1  = (const float*)d_in[5];
    const float* m1   = (const float*)d_in[6];
    const float* v1   = (const float*)d_in[7];
    const float* ew2  = (const float*)d_in[8];
    const float* eb2  = (const float*)d_in[9];
    const float* g2   = (const float*)d_in[10];
    const float* be2  = (const float*)d_in[11];
    const float* m2   = (const float*)d_in[12];
    const float* v2   = (const float*)d_in[13];
    const float* ew3  = (const float*)d_in[14];
    const float* eb3  = (const float*)d_in[15];
    const float* g3   = (const float*)d_in[16];
    const float* be3  = (const float*)d_in[17];
    const float* m3   = (const float*)d_in[18];
    const float* v3   = (const float*)d_in[19];
    const float* kpw1 = (const float*)d_in[20];
    const float* kpb1 = (const float*)d_in[21];
    const float* kpw2 = (const float*)d_in[22];
    const float* kpb2 = (const float*)d_in[23];
    const float* cgw1 = (const float*)d_in[24];
    const float* cgb1 = (const float*)d_in[25];
    const float* cgw2 = (const float*)d_in[26];
    const float* cgb2 = (const float*)d_in[27];
    float* out = (float*)d_out;

    cudaFuncSetAttribute(enc_kernel, cudaFuncAttributeMaxDynamicSharedMemorySize,
                         ENC_SMEM_BYTES);

    prep_kernel<<<1, 256>>>(ew1, eb1, g1, be1, m1, v1,
                            ew2, eb2, g2, be2, m2, v2,
                            ew3, eb3, g3, be3, m3, v3);
    enc_kernel<<<dim3(NPTS/(ENC_TP*ENC_SUBT), NSLOT), ENC_THREADS, ENC_SMEM_BYTES>>>(src, tgt);
    kp_kernel<<<NSLOT, 128>>>(kpw1, kpb1, kpw2, kpb2);
    fps_init_kernel<<<dim3(4, NSLOT), 1024>>>(src, tgt);
    fps_kernel<<<NSLOT, 1024>>>(src, tgt, out);
    cage_kernel<<<NB, 128>>>(cgw1, cgb1, cgw2, cgb2);
    pmm_kernel<<<NB, 1024>>>(src);
    deform_kernel<<<dim3(NPTS/256, NB), 256>>>(src, out);
}

// round 11
// speedup vs baseline: 1.1827x; 1.0088x over previous
#include <cuda_runtime.h>
#include <cuda_bf16.h>
#include <math.h>
#include <cstdint>

#define NPTS   16384
#define NB     16
#define NSLOT  32          // 16 source + 16 target clouds
#define KKP    16
#define OUT_DEF (NB*NPTS*3)   // 786432
#define OUT_KP  (NB*KKP*3)    // 768
#define BN_EPS 1e-5f

// ----------------------------------------------------------------------------
// bf16 2-way split: v = h + m + r, |r| <= ~2^-18 |v|
// ----------------------------------------------------------------------------
__device__ __forceinline__ void bsplit2(float v, unsigned short &h, unsigned short &m) {
    __nv_bfloat16 bh = __float2bfloat16(v);
    float r = v - __bfloat162float(bh);
    __nv_bfloat16 bm = __float2bfloat16(r);
    h = __bfloat16_as_ushort(bh);
    m = __bfloat16_as_ushort(bm);
}
__device__ __forceinline__ void pack_split(float v0, float v1, uint32_t &ph, uint32_t &pm) {
    unsigned short h0, m0, h1, m1;
    bsplit2(v0, h0, m0); bsplit2(v1, h1, m1);
    ph = (uint32_t)h0 | ((uint32_t)h1 << 16);
    pm = (uint32_t)m0 | ((uint32_t)m1 << 16);
}

// bf16 m16n8k16 MMA, fp32 accumulate (baseline PTX, works on compute_103)
#define MMA_BF16(acc, A, B) \
    asm volatile("mma.sync.aligned.m16n8k16.row.col.f32.bf16.bf16.f32 " \
        "{%0,%1,%2,%3}, {%4,%5,%6,%7}, {%8,%9}, {%0,%1,%2,%3};" \
        : "+f"((acc)[0]), "+f"((acc)[1]), "+f"((acc)[2]), "+f"((acc)[3]) \
        : "r"((A)[0]), "r"((A)[1]), "r"((A)[2]), "r"((A)[3]), \
          "r"((B)[0]), "r"((B)[1]))

// 128-thread named barrier (pgrp groups run independently)
#define BAR_GRP(id) asm volatile("bar.sync %0, %1;" :: "r"(id), "r"(128) : "memory")

// ----------------------------------------------------------------------------
// Device scratch (no allocations allowed)
// ----------------------------------------------------------------------------
#define WS2 36   // W2 kpair stride (32 pairs + pad); banks 4g+tq conflict-free
#define WS3 68   // W3 kpair stride (64 pairs + pad)
#define HS1 36   // H1 kpair stride
#define HS2 68   // H2 kpair stride

__device__ float    g_w1f[64*3];
__device__ float    g_b1f[64];
__device__ uint32_t g_w2h[128*WS2];  // W2 split-hi, packed bf16x2 [n][kpair]
__device__ uint32_t g_w2m[128*WS2];  // W2 split-lo
__device__ float    g_b2f[128];
__device__ uint32_t g_w3h[128*WS3];
__device__ uint32_t g_w3m[128*WS3];
__device__ float    g_b3f[128];
__device__ int      g_lat[NSLOT*128];  // latent max (float bits; relu => >=0)
__device__ float    g_kp[NSLOT*48];
__device__ float    g_sel[NSLOT*48];
__device__ float    g_cage[NB*1536];
__device__ float    g_pmm[NB*6];
__device__ float    g_mind[NSLOT*NPTS]; // FPS initial min-dist (2 MB)

// ----------------------------------------------------------------------------
// Prep: fold BN into weights, 2-way bf16 split, pack k-pairs; zero latents
// ----------------------------------------------------------------------------
__global__ void prep_kernel(
    const float* w1, const float* b1, const float* g1, const float* be1,
    const float* m1, const float* v1,
    const float* w2, const float* b2, const float* g2, const float* be2,
    const float* m2, const float* v2,
    const float* w3, const float* b3, const float* g3, const float* be3,
    const float* m3, const float* v3)
{
    int t = threadIdx.x;
    for (int d = t; d < 64; d += 256) {
        float s = g1[d] * rsqrtf(v1[d] + BN_EPS);
        g_w1f[d*3+0] = w1[d*3+0]*s;
        g_w1f[d*3+1] = w1[d*3+1]*s;
        g_w1f[d*3+2] = w1[d*3+2]*s;
        g_b1f[d] = (b1[d]-m1[d])*s + be1[d];
    }
    for (int d = t; d < 128; d += 256) {
        float s2 = g2[d] * rsqrtf(v2[d] + BN_EPS);
        for (int k = 0; k < 64; k += 2) {
            uint32_t ph, pm;
            pack_split(w2[d*64+k]*s2, w2[d*64+k+1]*s2, ph, pm);
            g_w2h[d*WS2 + (k>>1)] = ph;
            g_w2m[d*WS2 + (k>>1)] = pm;
        }
        g_b2f[d] = (b2[d]-m2[d])*s2 + be2[d];
        float s3 = g3[d] * rsqrtf(v3[d] + BN_EPS);
        for (int k = 0; k < 128; k += 2) {
            uint32_t ph, pm;
            pack_split(w3[d*128+k]*s3, w3[d*128+k+1]*s3, ph, pm);
            g_w3h[d*WS3 + (k>>1)] = ph;
            g_w3m[d*WS3 + (k>>1)] = pm;
        }
        g_b3f[d] = (b3[d]-m3[d])*s3 + be3[d];
    }
    for (int i = t; i < NSLOT*128; i += 256) g_lat[i] = 0;
}

// ----------------------------------------------------------------------------
// Encoder: 3->64->128->128 MLP + segmented max, layers 2/3 on bf16 m16n8k16
// mma.sync, 2-way split, 3 terms (hh+hm+mh; ~1e-5 rel; only affects 32
// first-iteration FPS argmax decisions; validated R7/R8/R9).
// 512 threads (16 warps), subtile = 128 points. Warp (pgrp=w&3, nquad=w>>2)
// owns 32 pts x 32 dims -- identical fragment layout / strides / MMA order
// as the 457us R9 kernel.
// NEW: all dataflow is closed within a pgrp group (4 warps, 128 threads):
// sX/sH1/sH2 rows are produced and consumed only by the owning group, so the
// block-wide __syncthreads in the subtile loop are replaced by named barriers
// bar.sync(pgrp+1, 128). Groups free-run: one group's scalar L1/epilogue now
// overlaps other groups' HMMA, closing the ~21% tensor-idle gap.
// Latent max accumulates in registers; atomicMax once at kernel end
// (bit-identical: same value set, max is order-invariant).
// ----------------------------------------------------------------------------
#define ENC_TP   128
#define ENC_SUBT 4
#define ENC_THREADS 512
#define ENC_SMEM_U32 (2*128*WS2 + 2*128*WS3 + 2*128*HS1 + 2*128*HS2 + 384)
#define ENC_SMEM_BYTES (ENC_SMEM_U32*4)

extern __shared__ uint32_t enc_smem[];

__global__ __launch_bounds__(ENC_THREADS, 1)
void enc_kernel(const float* __restrict__ src, const float* __restrict__ tgt)
{
    uint32_t* sW2h = enc_smem;               // 128*WS2
    uint32_t* sW2m = sW2h + 128*WS2;
    uint32_t* sW3h = sW2m + 128*WS2;         // 128*WS3
    uint32_t* sW3m = sW3h + 128*WS3;
    uint32_t* sH1h = sW3m + 128*WS3;         // 128*HS1
    uint32_t* sH1m = sH1h + 128*HS1;
    uint32_t* sH2h = sH1m + 128*HS1;         // 128*HS2
    uint32_t* sH2m = sH2h + 128*HS2;
    float*    sX   = (float*)(sH2m + 128*HS2); // 4 groups x 96

    const int t     = threadIdx.x;
    const int warp  = t >> 5;
    const int lane  = t & 31;
    const int g     = lane >> 2;
    const int tq    = lane & 3;
    const int pgrp  = warp & 3;              // 0..3 -> point rows 32*pgrp..+31
    const int nquad = warp >> 2;             // 0..3 -> dim cols 32*nquad..+31
    const int pbase = pgrp * 32;
    const int nb    = nquad * 32;
    const int gt    = nquad*32 + lane;       // thread id within pgrp group (0..127)
    const int bar   = pgrp + 1;
    const int slot  = blockIdx.y;

    const float* pts = (slot < 16) ? (src + (size_t)slot*NPTS*3)
                                   : (tgt + (size_t)(slot-16)*NPTS*3);
    float* sXg = sX + pgrp*96;

    // stage pre-split weights
    for (int i = t; i < 128*WS2; i += ENC_THREADS) { sW2h[i] = g_w2h[i]; sW2m[i] = g_w2m[i]; }
    for (int i = t; i < 128*WS3; i += ENC_THREADS) { sW3h[i] = g_w3h[i]; sW3m[i] = g_w3m[i]; }

    // per-thread biases for this warp's n-tiles (accumulator cols 2tq,2tq+1)
    float bias2[4][2], bias3[4][2];
    #pragma unroll
    for (int nt = 0; nt < 4; nt++) {
        bias2[nt][0] = g_b2f[nb + nt*8 + 2*tq];
        bias2[nt][1] = g_b2f[nb + nt*8 + 2*tq + 1];
        bias3[nt][0] = g_b3f[nb + nt*8 + 2*tq];
        bias3[nt][1] = g_b3f[nb + nt*8 + 2*tq + 1];
    }

    // per-warp latent max accumulators (col pair 2tq,2tq+1 per nt; >=0 init
    // implements the final relu since all maxed values pass through fmaxf)
    float macc[4][2];
    #pragma unroll
    for (int nt = 0; nt < 4; nt++) { macc[nt][0] = 0.f; macc[nt][1] = 0.f; }

    __syncthreads();   // weights visible to all groups

    for (int st = 0; st < ENC_SUBT; st++) {
        const int p0 = (blockIdx.x * ENC_SUBT + st) * ENC_TP;
        BAR_GRP(bar);  // group's prior readers of sX/sH1 done
        // group loads its own 32 points (96 floats)
        if (gt < 96) sXg[gt] = pts[(size_t)(p0 + pbase)*3 + gt];
        BAR_GRP(bar);

        // Layer 1 (scalar): group's 32 rows x 32 d-pairs -> split -> packed H1
        for (int i = gt; i < 32*32; i += 128) {
            int r = i >> 5, dp = i & 31;
            int p = pbase + r;
            int d0 = 2*dp;
            float x = sXg[r*3+0], y = sXg[r*3+1], z = sXg[r*3+2];
            float v0 = fmaxf(g_b1f[d0]   + x*g_w1f[d0*3+0] + y*g_w1f[d0*3+1] + z*g_w1f[d0*3+2], 0.f);
            float v1 = fmaxf(g_b1f[d0+1] + x*g_w1f[d0*3+3] + y*g_w1f[d0*3+4] + z*g_w1f[d0*3+5], 0.f);
            uint32_t ph, pm;
            pack_split(v0, v1, ph, pm);
            sH1h[p*HS1 + dp] = ph;
            sH1m[p*HS1 + dp] = pm;
        }
        BAR_GRP(bar);

        // ---------------- Layer 2: K=64 (4 k16 steps) ----------------
        {
            float acc[2][4][4];
            #pragma unroll
            for (int nt = 0; nt < 4; nt++)
                #pragma unroll
                for (int mg = 0; mg < 2; mg++) {
                    acc[mg][nt][0] = bias2[nt][0]; acc[mg][nt][1] = bias2[nt][1];
                    acc[mg][nt][2] = bias2[nt][0]; acc[mg][nt][3] = bias2[nt][1];
                }
            #pragma unroll
            for (int ks = 0; ks < 4; ks++) {
                const int kp0 = ks*8;
                uint32_t ah[2][4], am[2][4];
                #pragma unroll
                for (int mg = 0; mg < 2; mg++) {
                    const uint32_t* r0h = sH1h + (pbase + mg*16 + g)*HS1 + kp0;
                    const uint32_t* r0m = sH1m + (pbase + mg*16 + g)*HS1 + kp0;
                    ah[mg][0] = r0h[tq];            am[mg][0] = r0m[tq];
                    ah[mg][1] = r0h[8*HS1 + tq];    am[mg][1] = r0m[8*HS1 + tq];
                    ah[mg][2] = r0h[tq + 4];        am[mg][2] = r0m[tq + 4];
                    ah[mg][3] = r0h[8*HS1 + tq+4];  am[mg][3] = r0m[8*HS1 + tq+4];
                }
                #pragma unroll
                for (int nt = 0; nt < 4; nt++) {
                    const uint32_t* wh = sW2h + (nb + nt*8 + g)*WS2 + kp0;
                    const uint32_t* wm = sW2m + (nb + nt*8 + g)*WS2 + kp0;
                    uint32_t bh[2] = { wh[tq], wh[tq+4] };
                    uint32_t bm[2] = { wm[tq], wm[tq+4] };
                    #pragma unroll
                    for (int mg = 0; mg < 2; mg++) {
                        MMA_BF16(acc[mg][nt], ah[mg], bh);
                        MMA_BF16(acc[mg][nt], ah[mg], bm);
                        MMA_BF16(acc[mg][nt], am[mg], bh);
                    }
                }
            }
            // relu + split + packed store H2 (cols 2tq,2tq+1 form one pair)
            #pragma unroll
            for (int mg = 0; mg < 2; mg++)
                #pragma unroll
                for (int nt = 0; nt < 4; nt++) {
                    int row0 = pbase + mg*16 + g;
                    int cp   = (nb >> 1) + nt*4 + tq;    // column-pair index
                    uint32_t ph, pm;
                    pack_split(fmaxf(acc[mg][nt][0], 0.f), fmaxf(acc[mg][nt][1], 0.f), ph, pm);
                    sH2h[row0*HS2 + cp] = ph;
                    sH2m[row0*HS2 + cp] = pm;
                    pack_split(fmaxf(acc[mg][nt][2], 0.f), fmaxf(acc[mg][nt][3], 0.f), ph, pm);
                    sH2h[(row0+8)*HS2 + cp] = ph;
                    sH2m[(row0+8)*HS2 + cp] = pm;
                }
        }
        BAR_GRP(bar);

        // ---------------- Layer 3: K=128 (8 k16 steps) + fused max ----
        {
            float acc[2][4][4];
            #pragma unroll
            for (int nt = 0; nt < 4; nt++)
                #pragma unroll
                for (int mg = 0; mg < 2; mg++) {
                    acc[mg][nt][0] = bias3[nt][0]; acc[mg][nt][1] = bias3[nt][1];
                    acc[mg][nt][2] = bias3[nt][0]; acc[mg][nt][3] = bias3[nt][1];
                }
            #pragma unroll
            for (int ks = 0; ks < 8; ks++) {
                const int kp0 = ks*8;
                uint32_t ah[2][4], am[2][4];
                #pragma unroll
                for (int mg = 0; mg < 2; mg++) {
                    const uint32_t* r0h = sH2h + (pbase + mg*16 + g)*HS2 + kp0;
                    const uint32_t* r0m = sH2m + (pbase + mg*16 + g)*HS2 + kp0;
                    ah[mg][0] = r0h[tq];            am[mg][0] = r0m[tq];
                    ah[mg][1] = r0h[8*HS2 + tq];    am[mg][1] = r0m[8*HS2 + tq];
                    ah[mg][2] = r0h[tq + 4];        am[mg][2] = r0m[tq + 4];
                    ah[mg][3] = r0h[8*HS2 + tq+4];  am[mg][3] = r0m[8*HS2 + tq+4];
                }
                #pragma unroll
                for (int nt = 0; nt < 4; nt++) {
                    const uint32_t* wh = sW3h + (nb + nt*8 + g)*WS3 + kp0;
                    const uint32_t* wm = sW3m + (nb + nt*8 + g)*WS3 + kp0;
                    uint32_t bh[2] = { wh[tq], wh[tq+4] };
                    uint32_t bm[2] = { wm[tq], wm[tq+4] };
                    #pragma unroll
                    for (int mg = 0; mg < 2; mg++) {
                        MMA_BF16(acc[mg][nt], ah[mg], bh);
                        MMA_BF16(acc[mg][nt], ah[mg], bm);
                        MMA_BF16(acc[mg][nt], am[mg], bh);
                    }
                }
            }
            // max over this warp's 32 rows, accumulate into register maxes
            #pragma unroll
            for (int nt = 0; nt < 4; nt++) {
                float m0 = fmaxf(fmaxf(acc[0][nt][0], acc[0][nt][2]),
                                 fmaxf(acc[1][nt][0], acc[1][nt][2]));
                float m1 = fmaxf(fmaxf(acc[0][nt][1], acc[0][nt][3]),
                                 fmaxf(acc[1][nt][1], acc[1][nt][3]));
                #pragma unroll
                for (int o = 4; o < 32; o <<= 1) {
                    m0 = fmaxf(m0, __shfl_xor_sync(0xffffffffu, m0, o));
                    m1 = fmaxf(m1, __shfl_xor_sync(0xffffffffu, m1, o));
                }
                macc[nt][0] = fmaxf(macc[nt][0], m0);
                macc[nt][1] = fmaxf(macc[nt][1], m1);
            }
        }
    }

    // one atomic flush at kernel end (lanes g==0: tq = 0..3 hold distinct cols)
    if (g == 0) {
        #pragma unroll
        for (int nt = 0; nt < 4; nt++) {
            atomicMax(&g_lat[slot*128 + nb + nt*8 + 2*tq],     __float_as_int(macc[nt][0]));
            atomicMax(&g_lat[slot*128 + nb + nt*8 + 2*tq + 1], __float_as_int(macc[nt][1]));
        }
    }
}

// ----------------------------------------------------------------------------
// Keypoint MLP: lat[128] -> relu(128) -> 48
// ----------------------------------------------------------------------------
__global__ void kp_kernel(const float* __restrict__ kpw1, const float* __restrict__ kpb1,
                          const float* __restrict__ kpw2, const float* __restrict__ kpb2)
{
    __shared__ float latS[128];
    __shared__ float h[128];
    int slot = blockIdx.x, t = threadIdx.x;
    latS[t] = __int_as_float(g_lat[slot*128 + t]);
    __syncthreads();
    float a = kpb1[t];
    for (int k = 0; k < 128; k++) a = fmaf(latS[k], kpw1[t*128+k], a);
    h[t] = fmaxf(a, 0.f);
    __syncthreads();
    if (t < 48) {
        float o = kpb2[t];
        for (int k = 0; k < 128; k++) o = fmaf(h[k], kpw2[t*128+k], o);
        g_kp[slot*48 + t] = o;
    }
}

// ----------------------------------------------------------------------------
// FPS init: d0 = min dist to 16 MLP keypoints, spread over 128 blocks
// (identical expression order to the in-fps version -> same rounding).
// ----------------------------------------------------------------------------
__global__ __launch_bounds__(1024)
void fps_init_kernel(const float* __restrict__ src, const float* __restrict__ tgt)
{
    const int chunk = blockIdx.x, slot = blockIdx.y, t = threadIdx.x;
    const float* pts = (slot < 16) ? (src + (size_t)slot*NPTS*3)
                                   : (tgt + (size_t)(slot-16)*NPTS*3);
    __shared__ float skp[48];
    if (t < 48) skp[t] = g_kp[slot*48 + t];
    __syncthreads();

    const int base = chunk * 4096;
    #pragma unroll
    for (int i = 0; i < 4; i++) {
        int n = base + i*1024 + t;
        float px = pts[n*3+0], py = pts[n*3+1], pz = pts[n*3+2];
        float best = 1e30f;
        #pragma unroll
        for (int k = 0; k < 16; k++) {
            float dx = px-skp[k*3+0], dy = py-skp[k*3+1], dz = pz-skp[k*3+2];
            best = fminf(best, dx*dx + dy*dy + dz*dz);
        }
        g_mind[slot*NPTS + n] = best;
    }
}

// ----------------------------------------------------------------------------
// FPS: per cloud, 16 iterative argmax selections.
// jnp.argmax first-occurrence tie-break preserved (prefer smaller index).
// ----------------------------------------------------------------------------
__global__ __launch_bounds__(1024)
void fps_kernel(const float* __restrict__ src, const float* __restrict__ tgt,
                float* __restrict__ out)
{
    const int slot = blockIdx.x, t = threadIdx.x;
    const float* pts = (slot < 16) ? (src + (size_t)slot*NPTS*3)
                                   : (tgt + (size_t)(slot-16)*NPTS*3);
    float* kout = (slot < 16) ? (out + OUT_DEF + slot*48)
                              : (out + OUT_DEF + OUT_KP + (slot-16)*48);

    __shared__ float sredV[32];
    __shared__ int   sredI[32];
    __shared__ float selS[3];

    float px[16], py[16], pz[16], mind[16];
    #pragma unroll
    for (int i = 0; i < 16; i++) {
        int n = t + i*1024;
        px[i] = pts[n*3+0]; py[i] = pts[n*3+1]; pz[i] = pts[n*3+2];
        mind[i] = g_mind[slot*NPTS + n];
    }

    for (int it = 0; it < 16; it++) {
        float bv = -1e30f; int bi = 0x7fffffff;
        #pragma unroll
        for (int i = 0; i < 16; i++) {
            if (mind[i] > bv) { bv = mind[i]; bi = t + i*1024; }
        }
        #pragma unroll
        for (int o = 16; o > 0; o >>= 1) {
            float ov = __shfl_down_sync(0xffffffffu, bv, o);
            int   oi = __shfl_down_sync(0xffffffffu, bi, o);
            if (ov > bv || (ov == bv && oi < bi)) { bv = ov; bi = oi; }
        }
        if ((t & 31) == 0) { sredV[t>>5] = bv; sredI[t>>5] = bi; }
        __syncthreads();
        if (t < 32) {
            bv = sredV[t]; bi = sredI[t];
            #pragma unroll
            for (int o = 16; o > 0; o >>= 1) {
                float ov = __shfl_down_sync(0xffffffffu, bv, o);
                int   oi = __shfl_down_sync(0xffffffffu, bi, o);
                if (ov > bv || (ov == bv && oi < bi)) { bv = ov; bi = oi; }
            }
            if (t == 0) {
                float sx = pts[bi*3+0], sy = pts[bi*3+1], sz = pts[bi*3+2];
                selS[0] = sx; selS[1] = sy; selS[2] = sz;
                kout[it*3+0] = sx; kout[it*3+1] = sy; kout[it*3+2] = sz;
                g_sel[slot*48 + it*3+0] = sx;
                g_sel[slot*48 + it*3+1] = sy;
                g_sel[slot*48 + it*3+2] = sz;
            }
        }
        __syncthreads();
        float sx = selS[0], sy = selS[1], sz = selS[2];
        #pragma unroll
        for (int i = 0; i < 16; i++) {
            float dx = px[i]-sx, dy = py[i]-sy, dz = pz[i]-sz;
            float d = dx*dx + dy*dy + dz*dz;
            mind[i] = (it == 0) ? d : fminf(mind[i], d);  // it==0: REPLACE (ref)
        }
    }
}

// ----------------------------------------------------------------------------
// Cage MLP: diff[48] -> relu(128) -> 1536; build cage = grid + disp
// ----------------------------------------------------------------------------
__global__ void cage_kernel(const float* __restrict__ cgw1, const float* __restrict__ cgb1,
                            const float* __restrict__ cgw2, const float* __restrict__ cgb2)
{
    __shared__ float diff[48];
    __shared__ float h[128];
    int b = blockIdx.x, t = threadIdx.x;
    if (t < 48) diff[t] = g_sel[(16+b)*48 + t] - g_sel[b*48 + t];
    __syncthreads();
    float a = cgb1[t];
    for (int k = 0; k < 48; k++) a = fmaf(diff[k], cgw1[t*48+k], a);
    h[t] = fmaxf(a, 0.f);
    __syncthreads();
    for (int o = t; o < 1536; o += 128) {
        float acc = cgb2[o];
        for (int k = 0; k < 128; k++) acc = fmaf(h[k], cgw2[o*128+k], acc);
        int c = o % 3, cell = o / 3;
        int i = cell >> 6, j = (cell >> 3) & 7, kz = cell & 7;
        int li = (c == 0) ? i : (c == 1) ? j : kz;
        g_cage[b*1536 + o] = (float)li * (1.0f/7.0f) + acc;
    }
}

// ----------------------------------------------------------------------------
// Per-batch min/max of source points
// ----------------------------------------------------------------------------
__global__ __launch_bounds__(1024)
void pmm_kernel(const float* __restrict__ src)
{
    int b = blockIdx.x, t = threadIdx.x;
    const float* p = src + (size_t)b*NPTS*3;
    float mn0=1e30f, mn1=1e30f, mn2=1e30f, mx0=-1e30f, mx1=-1e30f, mx2=-1e30f;
    for (int n = t; n < NPTS; n += 1024) {
        float x = p[n*3+0], y = p[n*3+1], z = p[n*3+2];
        mn0 = fminf(mn0,x); mx0 = fmaxf(mx0,x);
        mn1 = fminf(mn1,y); mx1 = fmaxf(mx1,y);
        mn2 = fminf(mn2,z); mx2 = fmaxf(mx2,z);
    }
    #pragma unroll
    for (int o = 16; o > 0; o >>= 1) {
        mn0 = fminf(mn0, __shfl_down_sync(0xffffffffu, mn0, o));
        mn1 = fminf(mn1, __shfl_down_sync(0xffffffffu, mn1, o));
        mn2 = fminf(mn2, __shfl_down_sync(0xffffffffu, mn2, o));
        mx0 = fmaxf(mx0, __shfl_down_sync(0xffffffffu, mx0, o));
        mx1 = fmaxf(mx1, __shfl_down_sync(0xffffffffu, mx1, o));
        mx2 = fmaxf(mx2, __shfl_down_sync(0xffffffffu, mx2, o));
    }
    __shared__ float s[32][6];
    if ((t & 31) == 0) {
        s[t>>5][0]=mn0; s[t>>5][1]=mn1; s[t>>5][2]=mn2;
        s[t>>5][3]=mx0; s[t>>5][4]=mx1; s[t>>5][5]=mx2;
    }
    __syncthreads();
    if (t < 32) {
        mn0=s[t][0]; mn1=s[t][1]; mn2=s[t][2]; mx0=s[t][3]; mx1=s[t][4]; mx2=s[t][5];
        #pragma unroll
        for (int o = 16; o > 0; o >>= 1) {
            mn0 = fminf(mn0, __shfl_down_sync(0xffffffffu, mn0, o));
            mn1 = fminf(mn1, __shfl_down_sync(0xffffffffu, mn1, o));
            mn2 = fminf(mn2, __shfl_down_sync(0xffffffffu, mn2, o));
            mx0 = fmaxf(mx0, __shfl_down_sync(0xffffffffu, mx0, o));
            mx1 = fmaxf(mx1, __shfl_down_sync(0xffffffffu, mx1, o));
            mx2 = fmaxf(mx2, __shfl_down_sync(0xffffffffu, mx2, o));
        }
        if (t == 0) {
            g_pmm[b*6+0]=mn0; g_pmm[b*6+1]=mn1; g_pmm[b*6+2]=mn2;
            g_pmm[b*6+3]=mx0; g_pmm[b*6+4]=mx1; g_pmm[b*6+5]=mx2;
        }
    }
}

// ----------------------------------------------------------------------------
// Trilinear cage deform
// ----------------------------------------------------------------------------
__global__ void deform_kernel(const float* __restrict__ src, float* __restrict__ out)
{
    int b = blockIdx.y, t = threadIdx.x;
    __shared__ float cg[1536];
    __shared__ float pm[6];
    for (int i = t; i < 1536; i += 256) cg[i] = g_cage[b*1536 + i];
    if (t < 6) pm[t] = g_pmm[b*6 + t];
    __syncthreads();

    int n = blockIdx.x*256 + t;
    const float* p = src + ((size_t)b*NPTS + n)*3;
    float x = p[0], y = p[1], z = p[2];
    float tx = (x - pm[0]) / (pm[3]-pm[0] + 1e-6f) * 7.f;
    float ty = (y - pm[1]) / (pm[4]-pm[1] + 1e-6f) * 7.f;
    float tz = (z - pm[2]) / (pm[5]-pm[2] + 1e-6f) * 7.f;
    int u = min(max((int)tx, 0), 6);
    int v = min(max((int)ty, 0), 6);
    int w = min(max((int)tz, 0), 6);
    float wx = tx - (float)u, wy = ty - (float)v, wz = tz - (float)w;
    float ax = 1.f-wx, ay = 1.f-wy, az = 1.f-wz;

    int base = u*64 + v*8 + w;
    const float* c000 = &cg[(base     )*3];
    const float* c100 = &cg[(base + 64)*3];
    const float* c010 = &cg[(base +  8)*3];
    const float* c110 = &cg[(base + 72)*3];
    const float* c001 = &cg[(base +  1)*3];
    const float* c101 = &cg[(base + 65)*3];
    const float* c011 = &cg[(base +  9)*3];
    const float* c111 = &cg[(base + 73)*3];

    float w000 = ax*ay*az, w100 = wx*ay*az, w010 = ax*wy*az, w110 = wx*wy*az;
    float w001 = ax*ay*wz, w101 = wx*ay*wz, w011 = ax*wy*wz, w111 = wx*wy*wz;

    #pragma unroll
    for (int c = 0; c < 3; c++) {
        float d = w000*c000[c] + w100*c100[c] + w010*c010[c] + w110*c110[c]
                + w001*c001[c] + w101*c101[c] + w011*c011[c] + w111*c111[c];
        out[((size_t)b*NPTS + n)*3 + c] = p[c] + d;
    }
}

// ----------------------------------------------------------------------------
// Launch
// ----------------------------------------------------------------------------
extern "C" void kernel_launch(void* const* d_in, const int* in_sizes, int n_in,
                              void* d_out, int out_size)
{
    const float* src  = (const float*)d_in[0];
    const float* tgt  = (const float*)d_in[1];
    const float* ew1  = (const float*)d_in[2];
    const float* eb1  = (const float*)d_in[3];
    const float* g1   = (const float*)d_in[4];
    const float* be1  = (const float*)d_in[5];
    const float* m1   = (const float*)d_in[6];
    const float* v1   = (const float*)d_in[7];
    const float* ew2  = (const float*)d_in[8];
    const float* eb2  = (const float*)d_in[9];
    const float* g2   = (const float*)d_in[10];
    const float* be2  = (const float*)d_in[11];
    const float* m2   = (const float*)d_in[12];
    const float* v2   = (const float*)d_in[13];
    const float* ew3  = (const float*)d_in[14];
    const float* eb3  = (const float*)d_in[15];
    const float* g3   = (const float*)d_in[16];
    const float* be3  = (const float*)d_in[17];
    const float* m3   = (const float*)d_in[18];
    const float* v3   = (const float*)d_in[19];
    const float* kpw1 = (const float*)d_in[20];
    const float* kpb1 = (const float*)d_in[21];
    const float* kpw2 = (const float*)d_in[22];
    const float* kpb2 = (const float*)d_in[23];
    const float* cgw1 = (const float*)d_in[24];
    const float* cgb1 = (const float*)d_in[25];
    const float* cgw2 = (const float*)d_in[26];
    const float* cgb2 = (const float*)d_in[27];
    float* out = (float*)d_out;

    cudaFuncSetAttribute(enc_kernel, cudaFuncAttributeMaxDynamicSharedMemorySize,
                         ENC_SMEM_BYTES);

    prep_kernel<<<1, 256>>>(ew1, eb1, g1, be1, m1, v1,
                            ew2, eb2, g2, be2, m2, v2,
                            ew3, eb3, g3, be3, m3, v3);
    enc_kernel<<<dim3(NPTS/(ENC_TP*ENC_SUBT), NSLOT), ENC_THREADS, ENC_SMEM_BYTES>>>(src, tgt);
    kp_kernel<<<NSLOT, 128>>>(kpw1, kpb1, kpw2, kpb2);
    fps_init_kernel<<<dim3(4, NSLOT), 1024>>>(src, tgt);
    fps_kernel<<<NSLOT, 1024>>>(src, tgt, out);
    cage_kernel<<<NB, 128>>>(cgw1, cgb1, cgw2, cgb2);
    pmm_kernel<<<NB, 1024>>>(src);
    deform_kernel<<<dim3(NPTS/256, NB), 256>>>(src, out);
}

// round 12
// speedup vs baseline: 1.2938x; 1.0940x over previous
#include <cuda_runtime.h>
#include <cuda_bf16.h>
#include <math.h>
#include <cstdint>

#define NPTS   16384
#define NB     16
#define NSLOT  32          // 16 source + 16 target clouds
#define KKP    16
#define OUT_DEF (NB*NPTS*3)   // 786432
#define OUT_KP  (NB*KKP*3)    // 768
#define BN_EPS 1e-5f

// ----------------------------------------------------------------------------
// bf16 2-way split: v = h + m + r, |r| <= ~2^-18 |v|
// ----------------------------------------------------------------------------
__device__ __forceinline__ void bsplit2(float v, unsigned short &h, unsigned short &m) {
    __nv_bfloat16 bh = __float2bfloat16(v);
    float r = v - __bfloat162float(bh);
    __nv_bfloat16 bm = __float2bfloat16(r);
    h = __bfloat16_as_ushort(bh);
    m = __bfloat16_as_ushort(bm);
}
__device__ __forceinline__ void pack_split(float v0, float v1, uint32_t &ph, uint32_t &pm) {
    unsigned short h0, m0, h1, m1;
    bsplit2(v0, h0, m0); bsplit2(v1, h1, m1);
    ph = (uint32_t)h0 | ((uint32_t)h1 << 16);
    pm = (uint32_t)m0 | ((uint32_t)m1 << 16);
}

// bf16 m16n8k16 MMA, fp32 accumulate (baseline PTX, works on compute_103)
#define MMA_BF16(acc, A, B) \
    asm volatile("mma.sync.aligned.m16n8k16.row.col.f32.bf16.bf16.f32 " \
        "{%0,%1,%2,%3}, {%4,%5,%6,%7}, {%8,%9}, {%0,%1,%2,%3};" \
        : "+f"((acc)[0]), "+f"((acc)[1]), "+f"((acc)[2]), "+f"((acc)[3]) \
        : "r"((A)[0]), "r"((A)[1]), "r"((A)[2]), "r"((A)[3]), \
          "r"((B)[0]), "r"((B)[1]))

// 128-thread named barrier (pgrp groups run independently)
#define BAR_GRP(id) asm volatile("bar.sync %0, %1;" :: "r"(id), "r"(128) : "memory")

// ----------------------------------------------------------------------------
// Device scratch (no allocations allowed)
// ----------------------------------------------------------------------------
#define WS2 36   // W2 kpair stride (32 pairs + pad); banks 4g+tq conflict-free
#define WS3 68   // W3 kpair stride (64 pairs + pad)
#define HS1 36   // H1 kpair stride
#define HS2 68   // H2 kpair stride

__device__ float    g_w1f[64*3];
__device__ float    g_b1f[64];
__device__ uint32_t g_w2h[128*WS2];  // W2 split-hi, packed bf16x2 [n][kpair]
__device__ uint32_t g_w2m[128*WS2];  // W2 split-lo
__device__ float    g_b2f[128];
__device__ uint32_t g_w3h[128*WS3];
__device__ uint32_t g_w3m[128*WS3];
__device__ float    g_b3f[128];
__device__ int      g_lat[NSLOT*128];  // latent max (float bits; relu => >=0)
__device__ float    g_kp[NSLOT*48];
__device__ float    g_sel[NSLOT*48];
__device__ float    g_cage[NB*1536];
__device__ float    g_pmm[NB*6];
__device__ float    g_mind[NSLOT*NPTS]; // FPS initial min-dist (2 MB)

// ----------------------------------------------------------------------------
// Prep: fold BN into weights, 2-way bf16 split, pack k-pairs; zero latents.
// Parallelized over 32 blocks (block b owns output dims d = 4b..4b+3);
// identical per-element expressions as the single-block version.
// ----------------------------------------------------------------------------
__global__ void prep_kernel(
    const float* w1, const float* b1, const float* g1, const float* be1,
    const float* m1, const float* v1,
    const float* w2, const float* b2, const float* g2, const float* be2,
    const float* m2, const float* v2,
    const float* w3, const float* b3, const float* g3, const float* be3,
    const float* m3, const float* v3)
{
    const int b = blockIdx.x;      // 0..31
    const int t = threadIdx.x;     // 0..255

    if (b == 0) {
        for (int d = t; d < 64; d += 256) {
            float s = g1[d] * rsqrtf(v1[d] + BN_EPS);
            g_w1f[d*3+0] = w1[d*3+0]*s;
            g_w1f[d*3+1] = w1[d*3+1]*s;
            g_w1f[d*3+2] = w1[d*3+2]*s;
            g_b1f[d] = (b1[d]-m1[d])*s + be1[d];
        }
    }
    if (t < 128) g_lat[b*128 + t] = 0;   // 32*128 = 4096

    // W2: 4 dims x 32 kpairs = 128 tasks
    if (t < 128) {
        int d  = b*4 + (t >> 5);
        int kp = t & 31;
        int k  = 2*kp;
        float s2 = g2[d] * rsqrtf(v2[d] + BN_EPS);
        uint32_t ph, pm;
        pack_split(w2[d*64+k]*s2, w2[d*64+k+1]*s2, ph, pm);
        g_w2h[d*WS2 + kp] = ph;
        g_w2m[d*WS2 + kp] = pm;
    }
    // W3: 4 dims x 64 kpairs = 256 tasks
    {
        int d  = b*4 + (t >> 6);
        int kp = t & 63;
        int k  = 2*kp;
        float s3 = g3[d] * rsqrtf(v3[d] + BN_EPS);
        uint32_t ph, pm;
        pack_split(w3[d*128+k]*s3, w3[d*128+k+1]*s3, ph, pm);
        g_w3h[d*WS3 + kp] = ph;
        g_w3m[d*WS3 + kp] = pm;
    }
    if (t < 4) {
        int d = b*4 + t;
        float s2 = g2[d] * rsqrtf(v2[d] + BN_EPS);
        g_b2f[d] = (b2[d]-m2[d])*s2 + be2[d];
        float s3 = g3[d] * rsqrtf(v3[d] + BN_EPS);
        g_b3f[d] = (b3[d]-m3[d])*s3 + be3[d];
    }
}

// ----------------------------------------------------------------------------
// Encoder: 3->64->128->128 MLP + segmented max, layers 2/3 on bf16 m16n8k16
// mma.sync, 2-way split, 3 terms (hh+hm+mh). Unchanged from the 453us R10
// kernel (named pgrp barriers, register latent max, atomicMax at end).
// ----------------------------------------------------------------------------
#define ENC_TP   128
#define ENC_SUBT 4
#define ENC_THREADS 512
#define ENC_SMEM_U32 (2*128*WS2 + 2*128*WS3 + 2*128*HS1 + 2*128*HS2 + 384)
#define ENC_SMEM_BYTES (ENC_SMEM_U32*4)

extern __shared__ uint32_t enc_smem[];

__global__ __launch_bounds__(ENC_THREADS, 1)
void enc_kernel(const float* __restrict__ src, const float* __restrict__ tgt)
{
    uint32_t* sW2h = enc_smem;               // 128*WS2
    uint32_t* sW2m = sW2h + 128*WS2;
    uint32_t* sW3h = sW2m + 128*WS2;         // 128*WS3
    uint32_t* sW3m = sW3h + 128*WS3;
    uint32_t* sH1h = sW3m + 128*WS3;         // 128*HS1
    uint32_t* sH1m = sH1h + 128*HS1;
    uint32_t* sH2h = sH1m + 128*HS1;         // 128*HS2
    uint32_t* sH2m = sH2h + 128*HS2;
    float*    sX   = (float*)(sH2m + 128*HS2); // 4 groups x 96

    const int t     = threadIdx.x;
    const int warp  = t >> 5;
    const int lane  = t & 31;
    const int g     = lane >> 2;
    const int tq    = lane & 3;
    const int pgrp  = warp & 3;              // 0..3 -> point rows 32*pgrp..+31
    const int nquad = warp >> 2;             // 0..3 -> dim cols 32*nquad..+31
    const int pbase = pgrp * 32;
    const int nb    = nquad * 32;
    const int gt    = nquad*32 + lane;       // thread id within pgrp group (0..127)
    const int bar   = pgrp + 1;
    const int slot  = blockIdx.y;

    const float* pts = (slot < 16) ? (src + (size_t)slot*NPTS*3)
                                   : (tgt + (size_t)(slot-16)*NPTS*3);
    float* sXg = sX + pgrp*96;

    // stage pre-split weights
    for (int i = t; i < 128*WS2; i += ENC_THREADS) { sW2h[i] = g_w2h[i]; sW2m[i] = g_w2m[i]; }
    for (int i = t; i < 128*WS3; i += ENC_THREADS) { sW3h[i] = g_w3h[i]; sW3m[i] = g_w3m[i]; }

    // per-thread biases for this warp's n-tiles (accumulator cols 2tq,2tq+1)
    float bias2[4][2], bias3[4][2];
    #pragma unroll
    for (int nt = 0; nt < 4; nt++) {
        bias2[nt][0] = g_b2f[nb + nt*8 + 2*tq];
        bias2[nt][1] = g_b2f[nb + nt*8 + 2*tq + 1];
        bias3[nt][0] = g_b3f[nb + nt*8 + 2*tq];
        bias3[nt][1] = g_b3f[nb + nt*8 + 2*tq + 1];
    }

    // per-warp latent max accumulators (>=0 init implements the final relu)
    float macc[4][2];
    #pragma unroll
    for (int nt = 0; nt < 4; nt++) { macc[nt][0] = 0.f; macc[nt][1] = 0.f; }

    __syncthreads();   // weights visible to all groups

    for (int st = 0; st < ENC_SUBT; st++) {
        const int p0 = (blockIdx.x * ENC_SUBT + st) * ENC_TP;
        BAR_GRP(bar);  // group's prior readers of sX/sH1 done
        if (gt < 96) sXg[gt] = pts[(size_t)(p0 + pbase)*3 + gt];
        BAR_GRP(bar);

        // Layer 1 (scalar): group's 32 rows x 32 d-pairs -> split -> packed H1
        for (int i = gt; i < 32*32; i += 128) {
            int r = i >> 5, dp = i & 31;
            int p = pbase + r;
            int d0 = 2*dp;
            float x = sXg[r*3+0], y = sXg[r*3+1], z = sXg[r*3+2];
            float v0 = fmaxf(g_b1f[d0]   + x*g_w1f[d0*3+0] + y*g_w1f[d0*3+1] + z*g_w1f[d0*3+2], 0.f);
            float v1 = fmaxf(g_b1f[d0+1] + x*g_w1f[d0*3+3] + y*g_w1f[d0*3+4] + z*g_w1f[d0*3+5], 0.f);
            uint32_t ph, pm;
            pack_split(v0, v1, ph, pm);
            sH1h[p*HS1 + dp] = ph;
            sH1m[p*HS1 + dp] = pm;
        }
        BAR_GRP(bar);

        // ---------------- Layer 2: K=64 (4 k16 steps) ----------------
        {
            float acc[2][4][4];
            #pragma unroll
            for (int nt = 0; nt < 4; nt++)
                #pragma unroll
                for (int mg = 0; mg < 2; mg++) {
                    acc[mg][nt][0] = bias2[nt][0]; acc[mg][nt][1] = bias2[nt][1];
                    acc[mg][nt][2] = bias2[nt][0]; acc[mg][nt][3] = bias2[nt][1];
                }
            #pragma unroll
            for (int ks = 0; ks < 4; ks++) {
                const int kp0 = ks*8;
                uint32_t ah[2][4], am[2][4];
                #pragma unroll
                for (int mg = 0; mg < 2; mg++) {
                    const uint32_t* r0h = sH1h + (pbase + mg*16 + g)*HS1 + kp0;
                    const uint32_t* r0m = sH1m + (pbase + mg*16 + g)*HS1 + kp0;
                    ah[mg][0] = r0h[tq];            am[mg][0] = r0m[tq];
                    ah[mg][1] = r0h[8*HS1 + tq];    am[mg][1] = r0m[8*HS1 + tq];
                    ah[mg][2] = r0h[tq + 4];        am[mg][2] = r0m[tq + 4];
                    ah[mg][3] = r0h[8*HS1 + tq+4];  am[mg][3] = r0m[8*HS1 + tq+4];
                }
                #pragma unroll
                for (int nt = 0; nt < 4; nt++) {
                    const uint32_t* wh = sW2h + (nb + nt*8 + g)*WS2 + kp0;
                    const uint32_t* wm = sW2m + (nb + nt*8 + g)*WS2 + kp0;
                    uint32_t bh[2] = { wh[tq], wh[tq+4] };
                    uint32_t bm[2] = { wm[tq], wm[tq+4] };
                    #pragma unroll
                    for (int mg = 0; mg < 2; mg++) {
                        MMA_BF16(acc[mg][nt], ah[mg], bh);
                        MMA_BF16(acc[mg][nt], ah[mg], bm);
                        MMA_BF16(acc[mg][nt], am[mg], bh);
                    }
                }
            }
            // relu + split + packed store H2 (cols 2tq,2tq+1 form one pair)
            #pragma unroll
            for (int mg = 0; mg < 2; mg++)
                #pragma unroll
                for (int nt = 0; nt < 4; nt++) {
                    int row0 = pbase + mg*16 + g;
                    int cp   = (nb >> 1) + nt*4 + tq;    // column-pair index
                    uint32_t ph, pm;
                    pack_split(fmaxf(acc[mg][nt][0], 0.f), fmaxf(acc[mg][nt][1], 0.f), ph, pm);
                    sH2h[row0*HS2 + cp] = ph;
                    sH2m[row0*HS2 + cp] = pm;
                    pack_split(fmaxf(acc[mg][nt][2], 0.f), fmaxf(acc[mg][nt][3], 0.f), ph, pm);
                    sH2h[(row0+8)*HS2 + cp] = ph;
                    sH2m[(row0+8)*HS2 + cp] = pm;
                }
        }
        BAR_GRP(bar);

        // ---------------- Layer 3: K=128 (8 k16 steps) + fused max ----
        {
            float acc[2][4][4];
            #pragma unroll
            for (int nt = 0; nt < 4; nt++)
                #pragma unroll
                for (int mg = 0; mg < 2; mg++) {
                    acc[mg][nt][0] = bias3[nt][0]; acc[mg][nt][1] = bias3[nt][1];
                    acc[mg][nt][2] = bias3[nt][0]; acc[mg][nt][3] = bias3[nt][1];
                }
            #pragma unroll
            for (int ks = 0; ks < 8; ks++) {
                const int kp0 = ks*8;
                uint32_t ah[2][4], am[2][4];
                #pragma unroll
                for (int mg = 0; mg < 2; mg++) {
                    const uint32_t* r0h = sH2h + (pbase + mg*16 + g)*HS2 + kp0;
                    const uint32_t* r0m = sH2m + (pbase + mg*16 + g)*HS2 + kp0;
                    ah[mg][0] = r0h[tq];            am[mg][0] = r0m[tq];
                    ah[mg][1] = r0h[8*HS2 + tq];    am[mg][1] = r0m[8*HS2 + tq];
                    ah[mg][2] = r0h[tq + 4];        am[mg][2] = r0m[tq + 4];
                    ah[mg][3] = r0h[8*HS2 + tq+4];  am[mg][3] = r0m[8*HS2 + tq+4];
                }
                #pragma unroll
                for (int nt = 0; nt < 4; nt++) {
                    const uint32_t* wh = sW3h + (nb + nt*8 + g)*WS3 + kp0;
                    const uint32_t* wm = sW3m + (nb + nt*8 + g)*WS3 + kp0;
                    uint32_t bh[2] = { wh[tq], wh[tq+4] };
                    uint32_t bm[2] = { wm[tq], wm[tq+4] };
                    #pragma unroll
                    for (int mg = 0; mg < 2; mg++) {
                        MMA_BF16(acc[mg][nt], ah[mg], bh);
                        MMA_BF16(acc[mg][nt], ah[mg], bm);
                        MMA_BF16(acc[mg][nt], am[mg], bh);
                    }
                }
            }
            // max over this warp's 32 rows, accumulate into register maxes
            #pragma unroll
            for (int nt = 0; nt < 4; nt++) {
                float m0 = fmaxf(fmaxf(acc[0][nt][0], acc[0][nt][2]),
                                 fmaxf(acc[1][nt][0], acc[1][nt][2]));
                float m1 = fmaxf(fmaxf(acc[0][nt][1], acc[0][nt][3]),
                                 fmaxf(acc[1][nt][1], acc[1][nt][3]));
                #pragma unroll
                for (int o = 4; o < 32; o <<= 1) {
                    m0 = fmaxf(m0, __shfl_xor_sync(0xffffffffu, m0, o));
                    m1 = fmaxf(m1, __shfl_xor_sync(0xffffffffu, m1, o));
                }
                macc[nt][0] = fmaxf(macc[nt][0], m0);
                macc[nt][1] = fmaxf(macc[nt][1], m1);
            }
        }
    }

    // one atomic flush at kernel end (lanes g==0: tq = 0..3 hold distinct cols)
    if (g == 0) {
        #pragma unroll
        for (int nt = 0; nt < 4; nt++) {
            atomicMax(&g_lat[slot*128 + nb + nt*8 + 2*tq],     __float_as_int(macc[nt][0]));
            atomicMax(&g_lat[slot*128 + nb + nt*8 + 2*tq + 1], __float_as_int(macc[nt][1]));
        }
    }
}

// ----------------------------------------------------------------------------
// Keypoint MLP: lat[128] -> relu(128) -> 48
// ----------------------------------------------------------------------------
__global__ void kp_kernel(const float* __restrict__ kpw1, const float* __restrict__ kpb1,
                          const float* __restrict__ kpw2, const float* __restrict__ kpb2)
{
    __shared__ float latS[128];
    __shared__ float h[128];
    int slot = blockIdx.x, t = threadIdx.x;
    latS[t] = __int_as_float(g_lat[slot*128 + t]);
    __syncthreads();
    float a = kpb1[t];
    for (int k = 0; k < 128; k++) a = fmaf(latS[k], kpw1[t*128+k], a);
    h[t] = fmaxf(a, 0.f);
    __syncthreads();
    if (t < 48) {
        float o = kpb2[t];
        for (int k = 0; k < 128; k++) o = fmaf(h[k], kpw2[t*128+k], o);
        g_kp[slot*48 + t] = o;
    }
}

// ----------------------------------------------------------------------------
// FPS init: d0 = min dist to 16 MLP keypoints, spread over 128 blocks
// (identical expression order to the in-fps version -> same rounding).
// ----------------------------------------------------------------------------
__global__ __launch_bounds__(1024)
void fps_init_kernel(const float* __restrict__ src, const float* __restrict__ tgt)
{
    const int chunk = blockIdx.x, slot = blockIdx.y, t = threadIdx.x;
    const float* pts = (slot < 16) ? (src + (size_t)slot*NPTS*3)
                                   : (tgt + (size_t)(slot-16)*NPTS*3);
    __shared__ float skp[48];
    if (t < 48) skp[t] = g_kp[slot*48 + t];
    __syncthreads();

    const int base = chunk * 4096;
    #pragma unroll
    for (int i = 0; i < 4; i++) {
        int n = base + i*1024 + t;
        float px = pts[n*3+0], py = pts[n*3+1], pz = pts[n*3+2];
        float best = 1e30f;
        #pragma unroll
        for (int k = 0; k < 16; k++) {
            float dx = px-skp[k*3+0], dy = py-skp[k*3+1], dz = pz-skp[k*3+2];
            best = fminf(best, dx*dx + dy*dy + dz*dz);
        }
        g_mind[slot*NPTS + n] = best;
    }
}

// ----------------------------------------------------------------------------
// FPS: per cloud, 16 iterative argmax selections.
// Point cloud held in SHARED memory (192 KB): kills the register spill that
// made the old version reread 48 spilled floats/thread/iteration via local
// memory (regs capped at 64 by 1024-thread launch bounds). Expressions are
// identical -> selections bit-identical.
// jnp.argmax first-occurrence tie-break preserved (prefer smaller index).
// ----------------------------------------------------------------------------
#define FPS_SMEM_BYTES (NPTS*3*4)   // 196608

extern __shared__ float fps_sp[];

__global__ __launch_bounds__(1024)
void fps_kernel(const float* __restrict__ src, const float* __restrict__ tgt,
                float* __restrict__ out)
{
    const int slot = blockIdx.x, t = threadIdx.x;
    const float* pts = (slot < 16) ? (src + (size_t)slot*NPTS*3)
                                   : (tgt + (size_t)(slot-16)*NPTS*3);
    float* kout = (slot < 16) ? (out + OUT_DEF + slot*48)
                              : (out + OUT_DEF + OUT_KP + (slot-16)*48);

    __shared__ float sredV[32];
    __shared__ int   sredI[32];
    __shared__ float selS[3];

    // stage the cloud into shared (values identical to global)
    for (int i = t; i < NPTS*3; i += 1024) fps_sp[i] = pts[i];

    float mind[16];
    #pragma unroll
    for (int i = 0; i < 16; i++) mind[i] = g_mind[slot*NPTS + t + i*1024];
    __syncthreads();

    for (int it = 0; it < 16; it++) {
        float bv = -1e30f; int bi = 0x7fffffff;
        #pragma unroll
        for (int i = 0; i < 16; i++) {
            if (mind[i] > bv) { bv = mind[i]; bi = t + i*1024; }
        }
        #pragma unroll
        for (int o = 16; o > 0; o >>= 1) {
            float ov = __shfl_down_sync(0xffffffffu, bv, o);
            int   oi = __shfl_down_sync(0xffffffffu, bi, o);
            if (ov > bv || (ov == bv && oi < bi)) { bv = ov; bi = oi; }
        }
        if ((t & 31) == 0) { sredV[t>>5] = bv; sredI[t>>5] = bi; }
        __syncthreads();
        if (t < 32) {
            bv = sredV[t]; bi = sredI[t];
            #pragma unroll
            for (int o = 16; o > 0; o >>= 1) {
                float ov = __shfl_down_sync(0xffffffffu, bv, o);
                int   oi = __shfl_down_sync(0xffffffffu, bi, o);
                if (ov > bv || (ov == bv && oi < bi)) { bv = ov; bi = oi; }
            }
            if (t == 0) {
                float sx = fps_sp[bi*3+0], sy = fps_sp[bi*3+1], sz = fps_sp[bi*3+2];
                selS[0] = sx; selS[1] = sy; selS[2] = sz;
                kout[it*3+0] = sx; kout[it*3+1] = sy; kout[it*3+2] = sz;
                g_sel[slot*48 + it*3+0] = sx;
                g_sel[slot*48 + it*3+1] = sy;
                g_sel[slot*48 + it*3+2] = sz;
            }
        }
        __syncthreads();
        float sx = selS[0], sy = selS[1], sz = selS[2];
        #pragma unroll
        for (int i = 0; i < 16; i++) {
            int n = t + i*1024;
            float dx = fps_sp[n*3+0]-sx, dy = fps_sp[n*3+1]-sy, dz = fps_sp[n*3+2]-sz;
            float d = dx*dx + dy*dy + dz*dz;
            mind[i] = (it == 0) ? d : fminf(mind[i], d);  // it==0: REPLACE (ref)
        }
    }
}

// ----------------------------------------------------------------------------
// Cage MLP: diff[48] -> relu(128) -> 1536; build cage = grid + disp
// ----------------------------------------------------------------------------
__global__ void cage_kernel(const float* __restrict__ cgw1, const float* __restrict__ cgb1,
                            const float* __restrict__ cgw2, const float* __restrict__ cgb2)
{
    __shared__ float diff[48];
    __shared__ float h[128];
    int b = blockIdx.x, t = threadIdx.x;
    if (t < 48) diff[t] = g_sel[(16+b)*48 + t] - g_sel[b*48 + t];
    __syncthreads();
    float a = cgb1[t];
    for (int k = 0; k < 48; k++) a = fmaf(diff[k], cgw1[t*48+k], a);
    h[t] = fmaxf(a, 0.f);
    __syncthreads();
    for (int o = t; o < 1536; o += 128) {
        float acc = cgb2[o];
        for (int k = 0; k < 128; k++) acc = fmaf(h[k], cgw2[o*128+k], acc);
        int c = o % 3, cell = o / 3;
        int i = cell >> 6, j = (cell >> 3) & 7, kz = cell & 7;
        int li = (c == 0) ? i : (c == 1) ? j : kz;
        g_cage[b*1536 + o] = (float)li * (1.0f/7.0f) + acc;
    }
}

// ----------------------------------------------------------------------------
// Per-batch min/max of source points
// ----------------------------------------------------------------------------
__global__ __launch_bounds__(1024)
void pmm_kernel(const float* __restrict__ src)
{
    int b = blockIdx.x, t = threadIdx.x;
    const float* p = src + (size_t)b*NPTS*3;
    float mn0=1e30f, mn1=1e30f, mn2=1e30f, mx0=-1e30f, mx1=-1e30f, mx2=-1e30f;
    for (int n = t; n < NPTS; n += 1024) {
        float x = p[n*3+0], y = p[n*3+1], z = p[n*3+2];
        mn0 = fminf(mn0,x); mx0 = fmaxf(mx0,x);
        mn1 = fminf(mn1,y); mx1 = fmaxf(mx1,y);
        mn2 = fminf(mn2,z); mx2 = fmaxf(mx2,z);
    }
    #pragma unroll
    for (int o = 16; o > 0; o >>= 1) {
        mn0 = fminf(mn0, __shfl_down_sync(0xffffffffu, mn0, o));
        mn1 = fminf(mn1, __shfl_down_sync(0xffffffffu, mn1, o));
        mn2 = fminf(mn2, __shfl_down_sync(0xffffffffu, mn2, o));
        mx0 = fmaxf(mx0, __shfl_down_sync(0xffffffffu, mx0, o));
        mx1 = fmaxf(mx1, __shfl_down_sync(0xffffffffu, mx1, o));
        mx2 = fmaxf(mx2, __shfl_down_sync(0xffffffffu, mx2, o));
    }
    __shared__ float s[32][6];
    if ((t & 31) == 0) {
        s[t>>5][0]=mn0; s[t>>5][1]=mn1; s[t>>5][2]=mn2;
        s[t>>5][3]=mx0; s[t>>5][4]=mx1; s[t>>5][5]=mx2;
    }
    __syncthreads();
    if (t < 32) {
        mn0=s[t][0]; mn1=s[t][1]; mn2=s[t][2]; mx0=s[t][3]; mx1=s[t][4]; mx2=s[t][5];
        #pragma unroll
        for (int o = 16; o > 0; o >>= 1) {
            mn0 = fminf(mn0, __shfl_down_sync(0xffffffffu, mn0, o));
            mn1 = fminf(mn1, __shfl_down_sync(0xffffffffu, mn1, o));
            mn2 = fminf(mn2, __shfl_down_sync(0xffffffffu, mn2, o));
            mx0 = fmaxf(mx0, __shfl_down_sync(0xffffffffu, mx0, o));
            mx1 = fmaxf(mx1, __shfl_down_sync(0xffffffffu, mx1, o));
            mx2 = fmaxf(mx2, __shfl_down_sync(0xffffffffu, mx2, o));
        }
        if (t == 0) {
            g_pmm[b*6+0]=mn0; g_pmm[b*6+1]=mn1; g_pmm[b*6+2]=mn2;
            g_pmm[b*6+3]=mx0; g_pmm[b*6+4]=mx1; g_pmm[b*6+5]=mx2;
        }
    }
}

// ----------------------------------------------------------------------------
// Trilinear cage deform
// ----------------------------------------------------------------------------
__global__ void deform_kernel(const float* __restrict__ src, float* __restrict__ out)
{
    int b = blockIdx.y, t = threadIdx.x;
    __shared__ float cg[1536];
    __shared__ float pm[6];
    for (int i = t; i < 1536; i += 256) cg[i] = g_cage[b*1536 + i];
    if (t < 6) pm[t] = g_pmm[b*6 + t];
    __syncthreads();

    int n = blockIdx.x*256 + t;
    const float* p = src + ((size_t)b*NPTS + n)*3;
    float x = p[0], y = p[1], z = p[2];
    float tx = (x - pm[0]) / (pm[3]-pm[0] + 1e-6f) * 7.f;
    float ty = (y - pm[1]) / (pm[4]-pm[1] + 1e-6f) * 7.f;
    float tz = (z - pm[2]) / (pm[5]-pm[2] + 1e-6f) * 7.f;
    int u = min(max((int)tx, 0), 6);
    int v = min(max((int)ty, 0), 6);
    int w = min(max((int)tz, 0), 6);
    float wx = tx - (float)u, wy = ty - (float)v, wz = tz - (float)w;
    float ax = 1.f-wx, ay = 1.f-wy, az = 1.f-wz;

    int base = u*64 + v*8 + w;
    const float* c000 = &cg[(base     )*3];
    const float* c100 = &cg[(base + 64)*3];
    const float* c010 = &cg[(base +  8)*3];
    const float* c110 = &cg[(base + 72)*3];
    const float* c001 = &cg[(base +  1)*3];
    const float* c101 = &cg[(base + 65)*3];
    const float* c011 = &cg[(base +  9)*3];
    const float* c111 = &cg[(base + 73)*3];

    float w000 = ax*ay*az, w100 = wx*ay*az, w010 = ax*wy*az, w110 = wx*wy*az;
    float w001 = ax*ay*wz, w101 = wx*ay*wz, w011 = ax*wy*wz, w111 = wx*wy*wz;

    #pragma unroll
    for (int c = 0; c < 3; c++) {
        float d = w000*c000[c] + w100*c100[c] + w010*c010[c] + w110*c110[c]
                + w001*c001[c] + w101*c101[c] + w011*c011[c] + w111*c111[c];
        out[((size_t)b*NPTS + n)*3 + c] = p[c] + d;
    }
}

// ----------------------------------------------------------------------------
// Launch
// ----------------------------------------------------------------------------
extern "C" void kernel_launch(void* const* d_in, const int* in_sizes, int n_in,
                              void* d_out, int out_size)
{
    const float* src  = (const float*)d_in[0];
    const float* tgt  = (const float*)d_in[1];
    const float* ew1  = (const float*)d_in[2];
    const float* eb1  = (const float*)d_in[3];
    const float* g1   = (const float*)d_in[4];
    const float* be1  = (const float*)d_in[5];
    const float* m1   = (const float*)d_in[6];
    const float* v1   = (const float*)d_in[7];
    const float* ew2  = (const float*)d_in[8];
    const float* eb2  = (const float*)d_in[9];
    const float* g2   = (const float*)d_in[10];
    const float* be2  = (const float*)d_in[11];
    const float* m2   = (const float*)d_in[12];
    const float* v2   = (const float*)d_in[13];
    const float* ew3  = (const float*)d_in[14];
    const float* eb3  = (const float*)d_in[15];
    const float* g3   = (const float*)d_in[16];
    const float* be3  = (const float*)d_in[17];
    const float* m3   = (const float*)d_in[18];
    const float* v3   = (const float*)d_in[19];
    const float* kpw1 = (const float*)d_in[20];
    const float* kpb1 = (const float*)d_in[21];
    const float* kpw2 = (const float*)d_in[22];
    const float* kpb2 = (const float*)d_in[23];
    const float* cgw1 = (const float*)d_in[24];
    const float* cgb1 = (const float*)d_in[25];
    const float* cgw2 = (const float*)d_in[26];
    const float* cgb2 = (const float*)d_in[27];
    float* out = (float*)d_out;

    cudaFuncSetAttribute(enc_kernel, cudaFuncAttributeMaxDynamicSharedMemorySize,
                         ENC_SMEM_BYTES);
    cudaFuncSetAttribute(fps_kernel, cudaFuncAttributeMaxDynamicSharedMemorySize,
                         FPS_SMEM_BYTES);

    prep_kernel<<<32, 256>>>(ew1, eb1, g1, be1, m1, v1,
                             ew2, eb2, g2, be2, m2, v2,
                             ew3, eb3, g3, be3, m3, v3);
    enc_kernel<<<dim3(NPTS/(ENC_TP*ENC_SUBT), NSLOT), ENC_THREADS, ENC_SMEM_BYTES>>>(src, tgt);
    kp_kernel<<<NSLOT, 128>>>(kpw1, kpb1, kpw2, kpb2);
    fps_init_kernel<<<dim3(4, NSLOT), 1024>>>(src, tgt);
    fps_kernel<<<NSLOT, 1024, FPS_SMEM_BYTES>>>(src, tgt, out);
    cage_kernel<<<NB, 128>>>(cgw1, cgb1, cgw2, cgb2);
    pmm_kernel<<<NB, 1024>>>(src);
    deform_kernel<<<dim3(NPTS/256, NB), 256>>>(src, out);
}

// round 17
// speedup vs baseline: 1.3074x; 1.0105x over previous
#include <cuda_runtime.h>
#include <cuda_bf16.h>
#include <math.h>
#include <cstdint>

#define NPTS   16384
#define NB     16
#define NSLOT  32          // 16 source + 16 target clouds
#define KKP    16
#define OUT_DEF (NB*NPTS*3)   // 786432
#define OUT_KP  (NB*KKP*3)    // 768
#define BN_EPS 1e-5f

// ----------------------------------------------------------------------------
// bf16 2-way split: v = h + m + r, |r| <= ~2^-18 |v|
// ----------------------------------------------------------------------------
__device__ __forceinline__ void bsplit2(float v, unsigned short &h, unsigned short &m) {
    __nv_bfloat16 bh = __float2bfloat16(v);
    float r = v - __bfloat162float(bh);
    __nv_bfloat16 bm = __float2bfloat16(r);
    h = __bfloat16_as_ushort(bh);
    m = __bfloat16_as_ushort(bm);
}
__device__ __forceinline__ void pack_split(float v0, float v1, uint32_t &ph, uint32_t &pm) {
    unsigned short h0, m0, h1, m1;
    bsplit2(v0, h0, m0); bsplit2(v1, h1, m1);
    ph = (uint32_t)h0 | ((uint32_t)h1 << 16);
    pm = (uint32_t)m0 | ((uint32_t)m1 << 16);
}

// bf16 m16n8k16 MMA, fp32 accumulate (baseline PTX, works on compute_103)
#define MMA_BF16(acc, A, B) \
    asm volatile("mma.sync.aligned.m16n8k16.row.col.f32.bf16.bf16.f32 " \
        "{%0,%1,%2,%3}, {%4,%5,%6,%7}, {%8,%9}, {%0,%1,%2,%3};" \
        : "+f"((acc)[0]), "+f"((acc)[1]), "+f"((acc)[2]), "+f"((acc)[3]) \
        : "r"((A)[0]), "r"((A)[1]), "r"((A)[2]), "r"((A)[3]), \
          "r"((B)[0]), "r"((B)[1]))

// 128-thread named barrier (pgrp groups run independently)
#define BAR_GRP(id) asm volatile("bar.sync %0, %1;" :: "r"(id), "r"(128) : "memory")

// Monotone float<->uint encoding for exact atomic min/max (order-invariant)
__device__ __forceinline__ unsigned enc_f(float f) {
    int i = __float_as_int(f);
    return (i >= 0) ? ((unsigned)i | 0x80000000u) : ~(unsigned)i;
}
__device__ __forceinline__ float dec_f(unsigned u) {
    int i = (u & 0x80000000u) ? (int)(u & 0x7FFFFFFFu) : (int)~u;
    return __int_as_float(i);
}

// ----------------------------------------------------------------------------
// Device scratch (no allocations allowed)
// ----------------------------------------------------------------------------
#define WS2 36   // W2 kpair stride (32 pairs + pad); banks 4g+tq conflict-free
#define WS3 68   // W3 kpair stride (64 pairs + pad)
#define HS1 36   // H1 kpair stride
#define HS2 68   // H2 kpair stride

__device__ float    g_w1f[64*3];
__device__ float    g_b1f[64];
__device__ uint32_t g_w2h[128*WS2];  // W2 split-hi, packed bf16x2 [n][kpair]
__device__ uint32_t g_w2m[128*WS2];  // W2 split-lo
__device__ float    g_b2f[128];
__device__ uint32_t g_w3h[128*WS3];
__device__ uint32_t g_w3m[128*WS3];
__device__ float    g_b3f[128];
__device__ int      g_lat[NSLOT*128];  // latent max (float bits; relu => >=0)
__device__ float    g_kp[NSLOT*48];
__device__ float    g_sel[NSLOT*48];
__device__ float    g_cage[NB*1536];
__device__ unsigned g_pmme[NB*6];      // encoded min3,max3 (monotone uint keys)
__device__ float    g_mind[NSLOT*NPTS]; // FPS initial min-dist (2 MB)

// ----------------------------------------------------------------------------
// Prep: fold BN into weights, 2-way bf16 split, pack k-pairs; zero latents;
// init encoded pmm cells. 32 blocks (block b owns dims d = 4b..4b+3).
// ----------------------------------------------------------------------------
__global__ void prep_kernel(
    const float* w1, const float* b1, const float* g1, const float* be1,
    const float* m1, const float* v1,
    const float* w2, const float* b2, const float* g2, const float* be2,
    const float* m2, const float* v2,
    const float* w3, const float* b3, const float* g3, const float* be3,
    const float* m3, const float* v3)
{
    const int b = blockIdx.x;      // 0..31
    const int t = threadIdx.x;     // 0..255

    if (b == 0) {
        for (int d = t; d < 64; d += 256) {
            float s = g1[d] * rsqrtf(v1[d] + BN_EPS);
            g_w1f[d*3+0] = w1[d*3+0]*s;
            g_w1f[d*3+1] = w1[d*3+1]*s;
            g_w1f[d*3+2] = w1[d*3+2]*s;
            g_b1f[d] = (b1[d]-m1[d])*s + be1[d];
        }
    }
    if (b == 1 && t < NB*6) {
        // mins (idx%6 < 3) -> 0xFFFFFFFF (largest key), maxs -> 0
        g_pmme[t] = ((t % 6) < 3) ? 0xFFFFFFFFu : 0u;
    }
    if (t < 128) g_lat[b*128 + t] = 0;   // 32*128 = 4096

    // W2: 4 dims x 32 kpairs = 128 tasks
    if (t < 128) {
        int d  = b*4 + (t >> 5);
        int kp = t & 31;
        int k  = 2*kp;
        float s2 = g2[d] * rsqrtf(v2[d] + BN_EPS);
        uint32_t ph, pm;
        pack_split(w2[d*64+k]*s2, w2[d*64+k+1]*s2, ph, pm);
        g_w2h[d*WS2 + kp] = ph;
        g_w2m[d*WS2 + kp] = pm;
    }
    // W3: 4 dims x 64 kpairs = 256 tasks
    {
        int d  = b*4 + (t >> 6);
        int kp = t & 63;
        int k  = 2*kp;
        float s3 = g3[d] * rsqrtf(v3[d] + BN_EPS);
        uint32_t ph, pm;
        pack_split(w3[d*128+k]*s3, w3[d*128+k+1]*s3, ph, pm);
        g_w3h[d*WS3 + kp] = ph;
        g_w3m[d*WS3 + kp] = pm;
    }
    if (t < 4) {
        int d = b*4 + t;
        float s2 = g2[d] * rsqrtf(v2[d] + BN_EPS);
        g_b2f[d] = (b2[d]-m2[d])*s2 + be2[d];
        float s3 = g3[d] * rsqrtf(v3[d] + BN_EPS);
        g_b3f[d] = (b3[d]-m3[d])*s3 + be3[d];
    }
}

// ----------------------------------------------------------------------------
// Encoder: 3->64->128->128 MLP + segmented max, layers 2/3 on bf16 m16n8k16
// mma.sync, 2-way split, 3 terms (hh+hm+mh). Unchanged from the 414us R11
// kernel (named pgrp barriers, register latent max, atomicMax at end).
// ----------------------------------------------------------------------------
#define ENC_TP   128
#define ENC_SUBT 4
#define ENC_THREADS 512
#define ENC_SMEM_U32 (2*128*WS2 + 2*128*WS3 + 2*128*HS1 + 2*128*HS2 + 384)
#define ENC_SMEM_BYTES (ENC_SMEM_U32*4)

extern __shared__ uint32_t enc_smem[];

__global__ __launch_bounds__(ENC_THREADS, 1)
void enc_kernel(const float* __restrict__ src, const float* __restrict__ tgt)
{
    uint32_t* sW2h = enc_smem;               // 128*WS2
    uint32_t* sW2m = sW2h + 128*WS2;
    uint32_t* sW3h = sW2m + 128*WS2;         // 128*WS3
    uint32_t* sW3m = sW3h + 128*WS3;
    uint32_t* sH1h = sW3m + 128*WS3;         // 128*HS1
    uint32_t* sH1m = sH1h + 128*HS1;
    uint32_t* sH2h = sH1m + 128*HS1;         // 128*HS2
    uint32_t* sH2m = sH2h + 128*HS2;
    float*    sX   = (float*)(sH2m + 128*HS2); // 4 groups x 96

    const int t     = threadIdx.x;
    const int warp  = t >> 5;
    const int lane  = t & 31;
    const int g     = lane >> 2;
    const int tq    = lane & 3;
    const int pgrp  = warp & 3;              // 0..3 -> point rows 32*pgrp..+31
    const int nquad = warp >> 2;             // 0..3 -> dim cols 32*nquad..+31
    const int pbase = pgrp * 32;
    const int nb    = nquad * 32;
    const int gt    = nquad*32 + lane;       // thread id within pgrp group (0..127)
    const int bar   = pgrp + 1;
    const int slot  = blockIdx.y;

    const float* pts = (slot < 16) ? (src + (size_t)slot*NPTS*3)
                                   : (tgt + (size_t)(slot-16)*NPTS*3);
    float* sXg = sX + pgrp*96;

    // stage pre-split weights
    for (int i = t; i < 128*WS2; i += ENC_THREADS) { sW2h[i] = g_w2h[i]; sW2m[i] = g_w2m[i]; }
    for (int i = t; i < 128*WS3; i += ENC_THREADS) { sW3h[i] = g_w3h[i]; sW3m[i] = g_w3m[i]; }

    // per-thread biases for this warp's n-tiles (accumulator cols 2tq,2tq+1)
    float bias2[4][2], bias3[4][2];
    #pragma unroll
    for (int nt = 0; nt < 4; nt++) {
        bias2[nt][0] = g_b2f[nb + nt*8 + 2*tq];
        bias2[nt][1] = g_b2f[nb + nt*8 + 2*tq + 1];
        bias3[nt][0] = g_b3f[nb + nt*8 + 2*tq];
        bias3[nt][1] = g_b3f[nb + nt*8 + 2*tq + 1];
    }

    // per-warp latent max accumulators (>=0 init implements the final relu)
    float macc[4][2];
    #pragma unroll
    for (int nt = 0; nt < 4; nt++) { macc[nt][0] = 0.f; macc[nt][1] = 0.f; }

    __syncthreads();   // weights visible to all groups

    for (int st = 0; st < ENC_SUBT; st++) {
        const int p0 = (blockIdx.x * ENC_SUBT + st) * ENC_TP;
        BAR_GRP(bar);  // group's prior readers of sX/sH1 done
        if (gt < 96) sXg[gt] = pts[(size_t)(p0 + pbase)*3 + gt];
        BAR_GRP(bar);

        // Layer 1 (scalar): group's 32 rows x 32 d-pairs -> split -> packed H1
        for (int i = gt; i < 32*32; i += 128) {
            int r = i >> 5, dp = i & 31;
            int p = pbase + r;
            int d0 = 2*dp;
            float x = sXg[r*3+0], y = sXg[r*3+1], z = sXg[r*3+2];
            float v0 = fmaxf(g_b1f[d0]   + x*g_w1f[d0*3+0] + y*g_w1f[d0*3+1] + z*g_w1f[d0*3+2], 0.f);
            float v1 = fmaxf(g_b1f[d0+1] + x*g_w1f[d0*3+3] + y*g_w1f[d0*3+4] + z*g_w1f[d0*3+5], 0.f);
            uint32_t ph, pm;
            pack_split(v0, v1, ph, pm);
            sH1h[p*HS1 + dp] = ph;
            sH1m[p*HS1 + dp] = pm;
        }
        BAR_GRP(bar);

        // ---------------- Layer 2: K=64 (4 k16 steps) ----------------
        {
            float acc[2][4][4];
            #pragma unroll
            for (int nt = 0; nt < 4; nt++)
                #pragma unroll
                for (int mg = 0; mg < 2; mg++) {
                    acc[mg][nt][0] = bias2[nt][0]; acc[mg][nt][1] = bias2[nt][1];
                    acc[mg][nt][2] = bias2[nt][0]; acc[mg][nt][3] = bias2[nt][1];
                }
            #pragma unroll
            for (int ks = 0; ks < 4; ks++) {
                const int kp0 = ks*8;
                uint32_t ah[2][4], am[2][4];
                #pragma unroll
                for (int mg = 0; mg < 2; mg++) {
                    const uint32_t* r0h = sH1h + (pbase + mg*16 + g)*HS1 + kp0;
                    const uint32_t* r0m = sH1m + (pbase + mg*16 + g)*HS1 + kp0;
                    ah[mg][0] = r0h[tq];            am[mg][0] = r0m[tq];
                    ah[mg][1] = r0h[8*HS1 + tq];    am[mg][1] = r0m[8*HS1 + tq];
                    ah[mg][2] = r0h[tq + 4];        am[mg][2] = r0m[tq + 4];
                    ah[mg][3] = r0h[8*HS1 + tq+4];  am[mg][3] = r0m[8*HS1 + tq+4];
                }
                #pragma unroll
                for (int nt = 0; nt < 4; nt++) {
                    const uint32_t* wh = sW2h + (nb + nt*8 + g)*WS2 + kp0;
                    const uint32_t* wm = sW2m + (nb + nt*8 + g)*WS2 + kp0;
                    uint32_t bh[2] = { wh[tq], wh[tq+4] };
                    uint32_t bm[2] = { wm[tq], wm[tq+4] };
                    #pragma unroll
                    for (int mg = 0; mg < 2; mg++) {
                        MMA_BF16(acc[mg][nt], ah[mg], bh);
                        MMA_BF16(acc[mg][nt], ah[mg], bm);
                        MMA_BF16(acc[mg][nt], am[mg], bh);
                    }
                }
            }
            // relu + split + packed store H2 (cols 2tq,2tq+1 form one pair)
            #pragma unroll
            for (int mg = 0; mg < 2; mg++)
                #pragma unroll
                for (int nt = 0; nt < 4; nt++) {
                    int row0 = pbase + mg*16 + g;
                    int cp   = (nb >> 1) + nt*4 + tq;    // column-pair index
                    uint32_t ph, pm;
                    pack_split(fmaxf(acc[mg][nt][0], 0.f), fmaxf(acc[mg][nt][1], 0.f), ph, pm);
                    sH2h[row0*HS2 + cp] = ph;
                    sH2m[row0*HS2 + cp] = pm;
                    pack_split(fmaxf(acc[mg][nt][2], 0.f), fmaxf(acc[mg][nt][3], 0.f), ph, pm);
                    sH2h[(row0+8)*HS2 + cp] = ph;
                    sH2m[(row0+8)*HS2 + cp] = pm;
                }
        }
        BAR_GRP(bar);

        // ---------------- Layer 3: K=128 (8 k16 steps) + fused max ----
        {
            float acc[2][4][4];
            #pragma unroll
            for (int nt = 0; nt < 4; nt++)
                #pragma unroll
                for (int mg = 0; mg < 2; mg++) {
                    acc[mg][nt][0] = bias3[nt][0]; acc[mg][nt][1] = bias3[nt][1];
                    acc[mg][nt][2] = bias3[nt][0]; acc[mg][nt][3] = bias3[nt][1];
                }
            #pragma unroll
            for (int ks = 0; ks < 8; ks++) {
                const int kp0 = ks*8;
                uint32_t ah[2][4], am[2][4];
                #pragma unroll
                for (int mg = 0; mg < 2; mg++) {
                    const uint32_t* r0h = sH2h + (pbase + mg*16 + g)*HS2 + kp0;
                    const uint32_t* r0m = sH2m + (pbase + mg*16 + g)*HS2 + kp0;
                    ah[mg][0] = r0h[tq];            am[mg][0] = r0m[tq];
                    ah[mg][1] = r0h[8*HS2 + tq];    am[mg][1] = r0m[8*HS2 + tq];
                    ah[mg][2] = r0h[tq + 4];        am[mg][2] = r0m[tq + 4];
                    ah[mg][3] = r0h[8*HS2 + tq+4];  am[mg][3] = r0m[8*HS2 + tq+4];
                }
                #pragma unroll
                for (int nt = 0; nt < 4; nt++) {
                    const uint32_t* wh = sW3h + (nb + nt*8 + g)*WS3 + kp0;
                    const uint32_t* wm = sW3m + (nb + nt*8 + g)*WS3 + kp0;
                    uint32_t bh[2] = { wh[tq], wh[tq+4] };
                    uint32_t bm[2] = { wm[tq], wm[tq+4] };
                    #pragma unroll
                    for (int mg = 0; mg < 2; mg++) {
                        MMA_BF16(acc[mg][nt], ah[mg], bh);
                        MMA_BF16(acc[mg][nt], ah[mg], bm);
                        MMA_BF16(acc[mg][nt], am[mg], bh);
                    }
                }
            }
            // max over this warp's 32 rows, accumulate into register maxes
            #pragma unroll
            for (int nt = 0; nt < 4; nt++) {
                float m0 = fmaxf(fmaxf(acc[0][nt][0], acc[0][nt][2]),
                                 fmaxf(acc[1][nt][0], acc[1][nt][2]));
                float m1 = fmaxf(fmaxf(acc[0][nt][1], acc[0][nt][3]),
                                 fmaxf(acc[1][nt][1], acc[1][nt][3]));
                #pragma unroll
                for (int o = 4; o < 32; o <<= 1) {
                    m0 = fmaxf(m0, __shfl_xor_sync(0xffffffffu, m0, o));
                    m1 = fmaxf(m1, __shfl_xor_sync(0xffffffffu, m1, o));
                }
                macc[nt][0] = fmaxf(macc[nt][0], m0);
                macc[nt][1] = fmaxf(macc[nt][1], m1);
            }
        }
    }

    // one atomic flush at kernel end (lanes g==0: tq = 0..3 hold distinct cols)
    if (g == 0) {
        #pragma unroll
        for (int nt = 0; nt < 4; nt++) {
            atomicMax(&g_lat[slot*128 + nb + nt*8 + 2*tq],     __float_as_int(macc[nt][0]));
            atomicMax(&g_lat[slot*128 + nb + nt*8 + 2*tq + 1], __float_as_int(macc[nt][1]));
        }
    }
}

// ----------------------------------------------------------------------------
// Keypoint MLP: lat[128] -> relu(128) -> 48
// ----------------------------------------------------------------------------
__global__ void kp_kernel(const float* __restrict__ kpw1, const float* __restrict__ kpb1,
                          const float* __restrict__ kpw2, const float* __restrict__ kpb2)
{
    __shared__ float latS[128];
    __shared__ float h[128];
    int slot = blockIdx.x, t = threadIdx.x;
    latS[t] = __int_as_float(g_lat[slot*128 + t]);
    __syncthreads();
    float a = kpb1[t];
    for (int k = 0; k < 128; k++) a = fmaf(latS[k], kpw1[t*128+k], a);
    h[t] = fmaxf(a, 0.f);
    __syncthreads();
    if (t < 48) {
        float o = kpb2[t];
        for (int k = 0; k < 128; k++) o = fmaf(h[k], kpw2[t*128+k], o);
        g_kp[slot*48 + t] = o;
    }
}

// ----------------------------------------------------------------------------
// FPS init: d0 = min dist to 16 MLP keypoints, spread over 128 blocks
// (identical expression order to the in-fps version -> same rounding).
// Fused: src blocks (slot<16) also reduce per-batch min/max of their points
// and atomic-merge into encoded g_pmme (exact, order-invariant).
// ----------------------------------------------------------------------------
__global__ __launch_bounds__(1024)
void fps_init_kernel(const float* __restrict__ src, const float* __restrict__ tgt)
{
    const int chunk = blockIdx.x, slot = blockIdx.y, t = threadIdx.x;
    const float* pts = (slot < 16) ? (src + (size_t)slot*NPTS*3)
                                   : (tgt + (size_t)(slot-16)*NPTS*3);
    __shared__ float skp[48];
    if (t < 48) skp[t] = g_kp[slot*48 + t];
    __syncthreads();

    float mn0=1e30f, mn1=1e30f, mn2=1e30f, mx0=-1e30f, mx1=-1e30f, mx2=-1e30f;

    const int base = chunk * 4096;
    #pragma unroll
    for (int i = 0; i < 4; i++) {
        int n = base + i*1024 + t;
        float px = pts[n*3+0], py = pts[n*3+1], pz = pts[n*3+2];
        float best = 1e30f;
        #pragma unroll
        for (int k = 0; k < 16; k++) {
            float dx = px-skp[k*3+0], dy = py-skp[k*3+1], dz = pz-skp[k*3+2];
            best = fminf(best, dx*dx + dy*dy + dz*dz);
        }
        g_mind[slot*NPTS + n] = best;
        mn0 = fminf(mn0,px); mx0 = fmaxf(mx0,px);
        mn1 = fminf(mn1,py); mx1 = fmaxf(mx1,py);
        mn2 = fminf(mn2,pz); mx2 = fmaxf(mx2,pz);
    }

    // src blocks merge min/max into g_pmme (exact)
    if (slot < 16) {
        #pragma unroll
        for (int o = 16; o > 0; o >>= 1) {
            mn0 = fminf(mn0, __shfl_down_sync(0xffffffffu, mn0, o));
            mn1 = fminf(mn1, __shfl_down_sync(0xffffffffu, mn1, o));
            mn2 = fminf(mn2, __shfl_down_sync(0xffffffffu, mn2, o));
            mx0 = fmaxf(mx0, __shfl_down_sync(0xffffffffu, mx0, o));
            mx1 = fmaxf(mx1, __shfl_down_sync(0xffffffffu, mx1, o));
            mx2 = fmaxf(mx2, __shfl_down_sync(0xffffffffu, mx2, o));
        }
        __shared__ float s[32][6];
        if ((t & 31) == 0) {
            s[t>>5][0]=mn0; s[t>>5][1]=mn1; s[t>>5][2]=mn2;
            s[t>>5][3]=mx0; s[t>>5][4]=mx1; s[t>>5][5]=mx2;
        }
        __syncthreads();
        if (t < 32) {
            mn0=s[t][0]; mn1=s[t][1]; mn2=s[t][2]; mx0=s[t][3]; mx1=s[t][4]; mx2=s[t][5];
            #pragma unroll
            for (int o = 16; o > 0; o >>= 1) {
                mn0 = fminf(mn0, __shfl_down_sync(0xffffffffu, mn0, o));
                mn1 = fminf(mn1, __shfl_down_sync(0xffffffffu, mn1, o));
                mn2 = fminf(mn2, __shfl_down_sync(0xffffffffu, mn2, o));
                mx0 = fmaxf(mx0, __shfl_down_sync(0xffffffffu, mx0, o));
                mx1 = fmaxf(mx1, __shfl_down_sync(0xffffffffu, mx1, o));
                mx2 = fmaxf(mx2, __shfl_down_sync(0xffffffffu, mx2, o));
            }
            if (t == 0) {
                atomicMin(&g_pmme[slot*6+0], enc_f(mn0));
                atomicMin(&g_pmme[slot*6+1], enc_f(mn1));
                atomicMin(&g_pmme[slot*6+2], enc_f(mn2));
                atomicMax(&g_pmme[slot*6+3], enc_f(mx0));
                atomicMax(&g_pmme[slot*6+4], enc_f(mx1));
                atomicMax(&g_pmme[slot*6+5], enc_f(mx2));
            }
        }
    }
}

// ----------------------------------------------------------------------------
// FPS: per cloud, 16 iterative argmax selections. Cloud in shared memory,
// planar float2(xy) + float(z) layout: 2 LDS per point in the update loop.
// Values/expressions identical -> selections bit-identical.
// jnp.argmax first-occurrence tie-break preserved (prefer smaller index).
// ----------------------------------------------------------------------------
#define FPS_SMEM_BYTES (NPTS*3*4)   // 196608

extern __shared__ float fps_sp[];

__global__ __launch_bounds__(1024)
void fps_kernel(const float* __restrict__ src, const float* __restrict__ tgt,
                float* __restrict__ out)
{
    const int slot = blockIdx.x, t = threadIdx.x;
    const float* pts = (slot < 16) ? (src + (size_t)slot*NPTS*3)
                                   : (tgt + (size_t)(slot-16)*NPTS*3);
    float* kout = (slot < 16) ? (out + OUT_DEF + slot*48)
                              : (out + OUT_DEF + OUT_KP + (slot-16)*48);

    float2* sxy = (float2*)fps_sp;        // NPTS float2
    float*  szp = fps_sp + NPTS*2;        // NPTS float

    __shared__ float sredV[32];
    __shared__ int   sredI[32];
    __shared__ float selS[3];

    // stage cloud planar (values identical to global)
    for (int n = t; n < NPTS; n += 1024) {
        sxy[n] = make_float2(pts[n*3+0], pts[n*3+1]);
        szp[n] = pts[n*3+2];
    }

    float mind[16];
    #pragma unroll
    for (int i = 0; i < 16; i++) mind[i] = g_mind[slot*NPTS + t + i*1024];
    __syncthreads();

    for (int it = 0; it < 16; it++) {
        float bv = -1e30f; int bi = 0x7fffffff;
        #pragma unroll
        for (int i = 0; i < 16; i++) {
            if (mind[i] > bv) { bv = mind[i]; bi = t + i*1024; }
        }
        #pragma unroll
        for (int o = 16; o > 0; o >>= 1) {
            float ov = __shfl_down_sync(0xffffffffu, bv, o);
            int   oi = __shfl_down_sync(0xffffffffu, bi, o);
            if (ov > bv || (ov == bv && oi < bi)) { bv = ov; bi = oi; }
        }
        if ((t & 31) == 0) { sredV[t>>5] = bv; sredI[t>>5] = bi; }
        __syncthreads();
        if (t < 32) {
            bv = sredV[t]; bi = sredI[t];
            #pragma unroll
            for (int o = 16; o > 0; o >>= 1) {
                float ov = __shfl_down_sync(0xffffffffu, bv, o);
                int   oi = __shfl_down_sync(0xffffffffu, bi, o);
                if (ov > bv || (ov == bv && oi < bi)) { bv = ov; bi = oi; }
            }
            if (t == 0) {
                float2 sxyv = sxy[bi];
                float sx = sxyv.x, sy = sxyv.y, sz = szp[bi];
                selS[0] = sx; selS[1] = sy; selS[2] = sz;
                kout[it*3+0] = sx; kout[it*3+1] = sy; kout[it*3+2] = sz;
                g_sel[slot*48 + it*3+0] = sx;
                g_sel[slot*48 + it*3+1] = sy;
                g_sel[slot*48 + it*3+2] = sz;
            }
        }
        __syncthreads();
        float sx = selS[0], sy = selS[1], sz = selS[2];
        #pragma unroll
        for (int i = 0; i < 16; i++) {
            int n = t + i*1024;
            float2 xy = sxy[n];
            float dx = xy.x-sx, dy = xy.y-sy, dz = szp[n]-sz;
            float d = dx*dx + dy*dy + dz*dz;
            mind[i] = (it == 0) ? d : fminf(mind[i], d);  // it==0: REPLACE (ref)
        }
    }
}

// ----------------------------------------------------------------------------
// Cage MLP: diff[48] -> relu(128) -> 1536; build cage = grid + disp
// ----------------------------------------------------------------------------
__global__ void cage_kernel(const float* __restrict__ cgw1, const float* __restrict__ cgb1,
                            const float* __restrict__ cgw2, const float* __restrict__ cgb2)
{
    __shared__ float diff[48];
    __shared__ float h[128];
    int b = blockIdx.x, t = threadIdx.x;
    if (t < 48) diff[t] = g_sel[(16+b)*48 + t] - g_sel[b*48 + t];
    __syncthreads();
    float a = cgb1[t];
    for (int k = 0; k < 48; k++) a = fmaf(diff[k], cgw1[t*48+k], a);
    h[t] = fmaxf(a, 0.f);
    __syncthreads();
    for (int o = t; o < 1536; o += 128) {
        float acc = cgb2[o];
        for (int k = 0; k < 128; k++) acc = fmaf(h[k], cgw2[o*128+k], acc);
        int c = o % 3, cell = o / 3;
        int i = cell >> 6, j = (cell >> 3) & 7, kz = cell & 7;
        int li = (c == 0) ? i : (c == 1) ? j : kz;
        g_cage[b*1536 + o] = (float)li * (1.0f/7.0f) + acc;
    }
}

// ----------------------------------------------------------------------------
// Trilinear cage deform: 4 points per thread, float4 loads/stores
// (per-point expressions identical to the scalar version).
// ----------------------------------------------------------------------------
__global__ void deform_kernel(const float* __restrict__ src, float* __restrict__ out)
{
    int b = blockIdx.y, t = threadIdx.x;
    __shared__ float cg[1536];
    __shared__ float pm[6];
    for (int i = t; i < 1536; i += 256) cg[i] = g_cage[b*1536 + i];
    if (t < 6) pm[t] = dec_f(g_pmme[b*6 + t]);
    __syncthreads();

    const int n0 = (blockIdx.x*256 + t) * 4;
    const float4* p4 = (const float4*)(src + ((size_t)b*NPTS + n0)*3);
    float4 A = p4[0], B4 = p4[1], C = p4[2];
    float in[12] = { A.x, A.y, A.z, A.w, B4.x, B4.y, B4.z, B4.w, C.x, C.y, C.z, C.w };
    float res[12];

    const float inv_sx = 1.f / (pm[3]-pm[0] + 1e-6f);
    const float inv_sy = 1.f / (pm[4]-pm[1] + 1e-6f);
    const float inv_sz = 1.f / (pm[5]-pm[2] + 1e-6f);

    #pragma unroll
    for (int q = 0; q < 4; q++) {
        float x = in[q*3+0], y = in[q*3+1], z = in[q*3+2];
        float tx = (x - pm[0]) / (pm[3]-pm[0] + 1e-6f) * 7.f;
        float ty = (y - pm[1]) / (pm[4]-pm[1] + 1e-6f) * 7.f;
        float tz = (z - pm[2]) / (pm[5]-pm[2] + 1e-6f) * 7.f;
        (void)inv_sx; (void)inv_sy; (void)inv_sz;  // keep ref-identical division form
        int u = min(max((int)tx, 0), 6);
        int v = min(max((int)ty, 0), 6);
        int w = min(max((int)tz, 0), 6);
        float wx = tx - (float)u, wy = ty - (float)v, wz = tz - (float)w;
        float ax = 1.f-wx, ay = 1.f-wy, az = 1.f-wz;

        int base = u*64 + v*8 + w;
        const float* c000 = &cg[(base     )*3];
        const float* c100 = &cg[(base + 64)*3];
        const float* c010 = &cg[(base +  8)*3];
        const float* c110 = &cg[(base + 72)*3];
        const float* c001 = &cg[(base +  1)*3];
        const float* c101 = &cg[(base + 65)*3];
        const float* c011 = &cg[(base +  9)*3];
        const float* c111 = &cg[(base + 73)*3];

        float w000 = ax*ay*az, w100 = wx*ay*az, w010 = ax*wy*az, w110 = wx*wy*az;
        float w001 = ax*ay*wz, w101 = wx*ay*wz, w011 = ax*wy*wz, w111 = wx*wy*wz;

        #pragma unroll
        for (int c = 0; c < 3; c++) {
            float d = w000*c000[c] + w100*c100[c] + w010*c010[c] + w110*c110[c]
                    + w001*c001[c] + w101*c101[c] + w011*c011[c] + w111*c111[c];
            res[q*3+c] = in[q*3+c] + d;
        }
    }

    float4* o4 = (float4*)(out + ((size_t)b*NPTS + n0)*3);
    o4[0] = make_float4(res[0], res[1], res[2],  res[3]);
    o4[1] = make_float4(res[4], res[5], res[6],  res[7]);
    o4[2] = make_float4(res[8], res[9], res[10], res[11]);
}

// ----------------------------------------------------------------------------
// Launch
// ----------------------------------------------------------------------------
extern "C" void kernel_launch(void* const* d_in, const int* in_sizes, int n_in,
                              void* d_out, int out_size)
{
    const float* src  = (const float*)d_in[0];
    const float* tgt  = (const float*)d_in[1];
    const float* ew1  = (const float*)d_in[2];
    const float* eb1  = (const float*)d_in[3];
    const float* g1   = (const float*)d_in[4];
    const float* be1  = (const float*)d_in[5];
    const float* m1   = (const float*)d_in[6];
    const float* v1   = (const float*)d_in[7];
    const float* ew2  = (const float*)d_in[8];
    const float* eb2  = (const float*)d_in[9];
    const float* g2   = (const float*)d_in[10];
    const float* be2  = (const float*)d_in[11];
    const float* m2   = (const float*)d_in[12];
    const float* v2   = (const float*)d_in[13];
    const float* ew3  = (const float*)d_in[14];
    const float* eb3  = (const float*)d_in[15];
    const float* g3   = (const float*)d_in[16];
    const float* be3  = (const float*)d_in[17];
    const float* m3   = (const float*)d_in[18];
    const float* v3   = (const float*)d_in[19];
    const float* kpw1 = (const float*)d_in[20];
    const float* kpb1 = (const float*)d_in[21];
    const float* kpw2 = (const float*)d_in[22];
    const float* kpb2 = (const float*)d_in[23];
    const float* cgw1 = (const float*)d_in[24];
    const float* cgb1 = (const float*)d_in[25];
    const float* cgw2 = (const float*)d_in[26];
    const float* cgb2 = (const float*)d_in[27];
    float* out = (float*)d_out;

    cudaFuncSetAttribute(enc_kernel, cudaFuncAttributeMaxDynamicSharedMemorySize,
                         ENC_SMEM_BYTES);
    cudaFuncSetAttribute(fps_kernel, cudaFuncAttributeMaxDynamicSharedMemorySize,
                         FPS_SMEM_BYTES);

    prep_kernel<<<32, 256>>>(ew1, eb1, g1, be1, m1, v1,
                             ew2, eb2, g2, be2, m2, v2,
                             ew3, eb3, g3, be3, m3, v3);
    enc_kernel<<<dim3(NPTS/(ENC_TP*ENC_SUBT), NSLOT), ENC_THREADS, ENC_SMEM_BYTES>>>(src, tgt);
    kp_kernel<<<NSLOT, 128>>>(kpw1, kpb1, kpw2, kpb2);
    fps_init_kernel<<<dim3(4, NSLOT), 1024>>>(src, tgt);
    fps_kernel<<<NSLOT, 1024, FPS_SMEM_BYTES>>>(src, tgt, out);
    cage_kernel<<<NB, 128>>>(cgw1, cgb1, cgw2, cgb2);
    deform_kernel<<<dim3(NPTS/1024, NB), 256>>>(src, out);
}